// round 2
// baseline (speedup 1.0000x reference)
#include <cuda_runtime.h>

#define CN 512
#define KK 64
#define NPIX 16384
#define BB 8
#define BN_EPS 1e-5f

// ---------------- scratch (static device globals; no allocation) -------------
__device__ float g_W1[KK * CN];          // (lin0_w @ conv1_w)   [k][c]
__device__ float g_b1[KK];               // lin0_w @ conv1_b
__device__ float g_W2t[KK * CN];         // (conv2_w @ lin1_w)^T [k][c]
__device__ float g_attn[(size_t)BB * KK * NPIX];        // 32 MB
__device__ float g_y3[(size_t)BB * CN * NPIX];          // 256 MB
__device__ float g_bnsum[CN];
__device__ float g_bnsumsq[CN];
__device__ float g_scale[CN];
__device__ float g_shift[CN];

// ---------------- 1. precompute folded weights + zero BN accumulators -------
__global__ void prep_kernel(const float* __restrict__ conv1_w,
                            const float* __restrict__ conv1_b,
                            const float* __restrict__ lin0_w,
                            const float* __restrict__ lin1_w,
                            const float* __restrict__ conv2_w) {
    int tid = blockIdx.x * blockDim.x + threadIdx.x;
    if (tid < KK * CN) {
        int k = tid >> 9, c = tid & (CN - 1);
        float s = 0.f;
        for (int i = 0; i < CN; i++) s = fmaf(lin0_w[k * CN + i], conv1_w[i * CN + c], s);
        g_W1[tid] = s;
    } else if (tid < 2 * KK * CN) {
        int t = tid - KK * CN;
        int k = t >> 9, c = t & (CN - 1);
        float s = 0.f;
        for (int i = 0; i < CN; i++) s = fmaf(conv2_w[c * CN + i], lin1_w[i * KK + k], s);
        g_W2t[t] = s;  // stored [k][c]
    } else if (tid < 2 * KK * CN + KK) {
        int k = tid - 2 * KK * CN;
        float s = 0.f;
        for (int i = 0; i < CN; i++) s = fmaf(lin0_w[k * CN + i], conv1_b[i], s);
        g_b1[k] = s;
    } else if (tid < 2 * KK * CN + KK + 2 * CN) {
        int t = tid - (2 * KK * CN + KK);
        if (t < CN) g_bnsum[t] = 0.f;
        else        g_bnsumsq[t - CN] = 0.f;
    }
}

// ---------------- 2. attn_raw = W1 @ x + b1  (M=64, K=512, N per batch 16384)
#define A_TN 256
#define A_CH 32
__global__ __launch_bounds__(256) void attn_gemm_kernel(const float* __restrict__ x) {
    __shared__ float xs[A_CH][A_TN];    // 32 KB
    __shared__ float w1s[KK][A_CH];     // 8 KB
    int b = blockIdx.y;
    int n0 = blockIdx.x * A_TN;
    int tid = threadIdx.x;

    float acc[KK];
#pragma unroll
    for (int k = 0; k < KK; k++) acc[k] = 0.f;

    const float* xb = x + (size_t)b * CN * NPIX;
    for (int c0 = 0; c0 < CN; c0 += A_CH) {
#pragma unroll
        for (int i = tid; i < A_CH * A_TN; i += 256) {
            int cc = i >> 8, nn = i & 255;
            xs[cc][nn] = xb[(size_t)(c0 + cc) * NPIX + n0 + nn];
        }
#pragma unroll
        for (int i = tid; i < KK * A_CH; i += 256) {
            int k = i >> 5, cc = i & 31;
            w1s[k][cc] = g_W1[k * CN + c0 + cc];
        }
        __syncthreads();
#pragma unroll
        for (int cc = 0; cc < A_CH; cc += 4) {
            float x0 = xs[cc][tid], x1 = xs[cc + 1][tid];
            float x2 = xs[cc + 2][tid], x3 = xs[cc + 3][tid];
#pragma unroll
            for (int k = 0; k < KK; k++) {
                const float4 w = *(const float4*)&w1s[k][cc];
                acc[k] = fmaf(w.x, x0, fmaf(w.y, x1, fmaf(w.z, x2, fmaf(w.w, x3, acc[k]))));
            }
        }
        __syncthreads();
    }
    float* ab = g_attn + (size_t)b * KK * NPIX + n0 + tid;
#pragma unroll
    for (int k = 0; k < KK; k++) ab[(size_t)k * NPIX] = acc[k] + g_b1[k];
}

// ---------------- 3. softmax over n (one block per (b,k) row of 16384) ------
__global__ __launch_bounds__(256) void softmax_kernel() {
    int row = blockIdx.x;  // b*KK + k
    float* p = g_attn + (size_t)row * NPIX;
    int tid = threadIdx.x;

    float v[64];
    float m = -1e30f;
#pragma unroll
    for (int i = 0; i < 64; i++) {
        v[i] = p[tid + (i << 8)];
        m = fmaxf(m, v[i]);
    }
    __shared__ float red[8];
#pragma unroll
    for (int o = 16; o > 0; o >>= 1) m = fmaxf(m, __shfl_xor_sync(0xffffffffu, m, o));
    if ((tid & 31) == 0) red[tid >> 5] = m;
    __syncthreads();
    if (tid < 32) {
        float t = (tid < 8) ? red[tid] : -1e30f;
#pragma unroll
        for (int o = 4; o > 0; o >>= 1) t = fmaxf(t, __shfl_xor_sync(0xffffffffu, t, o));
        if (tid == 0) red[0] = t;
    }
    __syncthreads();
    m = red[0];
    __syncthreads();

    float s = 0.f;
#pragma unroll
    for (int i = 0; i < 64; i++) {
        v[i] = __expf(v[i] - m);
        s += v[i];
    }
#pragma unroll
    for (int o = 16; o > 0; o >>= 1) s += __shfl_xor_sync(0xffffffffu, s, o);
    if ((tid & 31) == 0) red[tid >> 5] = s;
    __syncthreads();
    if (tid < 32) {
        float t = (tid < 8) ? red[tid] : 0.f;
#pragma unroll
        for (int o = 4; o > 0; o >>= 1) t += __shfl_xor_sync(0xffffffffu, t, o);
        if (tid == 0) red[0] = t;
    }
    __syncthreads();
    float inv = 1.f / red[0];
#pragma unroll
    for (int i = 0; i < 64; i++) p[tid + (i << 8)] = v[i] * inv;
}

// ---------------- 4. y3 = W2 @ (attn / (eps + colsum_k))  M=512, K=64 -------
#define B_TN 128
#define B_TC 128
#define B_KCH 32
__global__ __launch_bounds__(256) void out_gemm_kernel() {
    __shared__ float as[B_KCH][B_TN];   // 16 KB
    __shared__ float ws[B_KCH][B_TC];   // 16 KB
    __shared__ float dsum[B_TN];
    int b = blockIdx.z;
    int c0 = blockIdx.y * B_TC;
    int n0 = blockIdx.x * B_TN;
    int tid = threadIdx.x;
    int tx = tid & 15, ty = tid >> 4;

    float acc[8][8];
#pragma unroll
    for (int i = 0; i < 8; i++)
#pragma unroll
        for (int j = 0; j < 8; j++) acc[i][j] = 0.f;
    if (tid < B_TN) dsum[tid] = 0.f;

    const float* ab = g_attn + (size_t)b * KK * NPIX;
    for (int k0 = 0; k0 < KK; k0 += B_KCH) {
        __syncthreads();
#pragma unroll
        for (int i = tid; i < B_KCH * B_TN; i += 256) {
            int kk = i >> 7, nn = i & 127;
            as[kk][nn] = ab[(size_t)(k0 + kk) * NPIX + n0 + nn];
        }
#pragma unroll
        for (int i = tid; i < B_KCH * B_TC; i += 256) {
            int kk = i >> 7, cc = i & 127;
            ws[kk][cc] = g_W2t[(k0 + kk) * CN + c0 + cc];
        }
        __syncthreads();
        if (tid < B_TN) {  // accumulate column L1 sums from the staged tile
            float s = 0.f;
#pragma unroll
            for (int kk = 0; kk < B_KCH; kk++) s += as[kk][tid];
            dsum[tid] += s;
        }
#pragma unroll
        for (int kk = 0; kk < B_KCH; kk++) {
            float4 a0 = *(const float4*)&as[kk][tx * 8];
            float4 a1 = *(const float4*)&as[kk][tx * 8 + 4];
            float4 w0 = *(const float4*)&ws[kk][ty * 8];
            float4 w1 = *(const float4*)&ws[kk][ty * 8 + 4];
            float av[8] = {a0.x, a0.y, a0.z, a0.w, a1.x, a1.y, a1.z, a1.w};
            float wv[8] = {w0.x, w0.y, w0.z, w0.w, w1.x, w1.y, w1.z, w1.w};
#pragma unroll
            for (int i = 0; i < 8; i++)
#pragma unroll
                for (int j = 0; j < 8; j++) acc[i][j] = fmaf(wv[i], av[j], acc[i][j]);
        }
    }
    __syncthreads();
    float inv[8];
#pragma unroll
    for (int j = 0; j < 8; j++) inv[j] = 1.f / (1e-9f + dsum[tx * 8 + j]);
#pragma unroll
    for (int i = 0; i < 8; i++) {
        float* yr = g_y3 + ((size_t)(b * CN + c0 + ty * 8 + i)) * NPIX + n0 + tx * 8;
        float4 o0, o1;
        o0.x = acc[i][0] * inv[0]; o0.y = acc[i][1] * inv[1];
        o0.z = acc[i][2] * inv[2]; o0.w = acc[i][3] * inv[3];
        o1.x = acc[i][4] * inv[4]; o1.y = acc[i][5] * inv[5];
        o1.z = acc[i][6] * inv[6]; o1.w = acc[i][7] * inv[7];
        *(float4*)yr = o0;
        *(float4*)(yr + 4) = o1;
    }
}

// ---------------- 5. BN batch statistics (per channel over b,n) -------------
__global__ __launch_bounds__(256) void bnstat_kernel() {
    int c = blockIdx.x >> 3;
    int b = blockIdx.x & 7;
    const float* p = g_y3 + ((size_t)(b * CN + c)) * NPIX;
    int tid = threadIdx.x;
    float s = 0.f, sq = 0.f;
    for (int i = tid; i < NPIX; i += 256) {
        float v = p[i];
        s += v;
        sq = fmaf(v, v, sq);
    }
    __shared__ float r1[8], r2[8];
#pragma unroll
    for (int o = 16; o > 0; o >>= 1) {
        s += __shfl_xor_sync(0xffffffffu, s, o);
        sq += __shfl_xor_sync(0xffffffffu, sq, o);
    }
    if ((tid & 31) == 0) { r1[tid >> 5] = s; r2[tid >> 5] = sq; }
    __syncthreads();
    if (tid == 0) {
        float a = 0.f, bq = 0.f;
        for (int w = 0; w < 8; w++) { a += r1[w]; bq += r2[w]; }
        atomicAdd(&g_bnsum[c], a);
        atomicAdd(&g_bnsumsq[c], bq);
    }
}

// ---------------- 6. fold BN into per-channel scale/shift -------------------
__global__ void bnscale_kernel(const float* __restrict__ gamma,
                               const float* __restrict__ beta) {
    int c = threadIdx.x + blockIdx.x * blockDim.x;
    if (c < CN) {
        const float cnt = (float)(BB * NPIX);
        float mean = g_bnsum[c] / cnt;
        float var = g_bnsumsq[c] / cnt - mean * mean;
        float sc = gamma[c] * rsqrtf(var + BN_EPS);
        g_scale[c] = sc;
        g_shift[c] = beta[c] - mean * sc;
    }
}

// ---------------- 7. out = relu(y3*scale + shift + x) -----------------------
__global__ __launch_bounds__(256) void final_kernel(const float* __restrict__ x,
                                                    float* __restrict__ out) {
    size_t i4 = (size_t)blockIdx.x * blockDim.x + threadIdx.x;
    const size_t total4 = (size_t)BB * CN * NPIX / 4;
    if (i4 >= total4) return;
    int c = (int)((i4 >> 12) & (CN - 1));
    float sc = g_scale[c], sh = g_shift[c];
    float4 y = ((const float4*)g_y3)[i4];
    float4 xi = ((const float4*)x)[i4];
    float4 o;
    o.x = fmaxf(fmaf(y.x, sc, sh) + xi.x, 0.f);
    o.y = fmaxf(fmaf(y.y, sc, sh) + xi.y, 0.f);
    o.z = fmaxf(fmaf(y.z, sc, sh) + xi.z, 0.f);
    o.w = fmaxf(fmaf(y.w, sc, sh) + xi.w, 0.f);
    ((float4*)out)[i4] = o;
}

// ---------------- launch -----------------------------------------------------
extern "C" void kernel_launch(void* const* d_in, const int* in_sizes, int n_in,
                              void* d_out, int out_size) {
    const float* x       = (const float*)d_in[0];
    const float* conv1_w = (const float*)d_in[1];
    const float* conv1_b = (const float*)d_in[2];
    const float* lin0_w  = (const float*)d_in[3];
    const float* lin1_w  = (const float*)d_in[4];
    const float* conv2_w = (const float*)d_in[5];
    const float* gamma   = (const float*)d_in[6];
    const float* beta    = (const float*)d_in[7];
    float* out = (float*)d_out;

    prep_kernel<<<(2 * KK * CN + KK + 2 * CN + 255) / 256, 256>>>(
        conv1_w, conv1_b, lin0_w, lin1_w, conv2_w);
    attn_gemm_kernel<<<dim3(NPIX / A_TN, BB), 256>>>(x);
    softmax_kernel<<<BB * KK, 256>>>();
    out_gemm_kernel<<<dim3(NPIX / B_TN, CN / B_TC, BB), 256>>>();
    bnstat_kernel<<<CN * BB, 256>>>();
    bnscale_kernel<<<2, 256>>>(gamma, beta);
    final_kernel<<<(int)(((size_t)BB * CN * NPIX / 4 + 255) / 256), 256>>>(x, out);
}

// round 3
// speedup vs baseline: 1.2566x; 1.2566x over previous
#include <cuda_runtime.h>

#define CN 512
#define KK 64
#define NPIX 16384
#define BB 8
#define BN_EPS 1e-5f

typedef unsigned long long u64;

__device__ __forceinline__ u64 ffma2(u64 a, u64 b, u64 c) {
    u64 d;
    asm("fma.rn.f32x2 %0, %1, %2, %3;" : "=l"(d) : "l"(a), "l"(b), "l"(c));
    return d;
}
__device__ __forceinline__ u64 pack2(float x, float y) {
    u64 v; asm("mov.b64 %0, {%1, %2};" : "=l"(v) : "f"(x), "f"(y)); return v;
}
__device__ __forceinline__ float2 unpack2(u64 v) {
    float2 f; asm("mov.b64 {%0, %1}, %2;" : "=f"(f.x), "=f"(f.y) : "l"(v)); return f;
}

// ---------------- scratch (static device globals; no allocation) -------------
__device__ float g_W1t[CN * KK];         // (lin0_w @ conv1_w)^T  [c][k]
__device__ float g_b1[KK];               // lin0_w @ conv1_b
__device__ float g_W2t[KK * CN];         // (conv2_w @ lin1_w)^T  [k][c]
__device__ float g_attn[(size_t)BB * KK * NPIX];        // 32 MB
__device__ float g_y3[(size_t)BB * CN * NPIX];          // 256 MB
__device__ float g_bnsum[CN];
__device__ float g_bnsumsq[CN];
__device__ float g_scale[CN];
__device__ float g_shift[CN];

// ---------------- 1. precompute folded weights + zero BN accumulators -------
__global__ void prep_kernel(const float* __restrict__ conv1_w,
                            const float* __restrict__ conv1_b,
                            const float* __restrict__ lin0_w,
                            const float* __restrict__ lin1_w,
                            const float* __restrict__ conv2_w) {
    int tid = blockIdx.x * blockDim.x + threadIdx.x;
    if (tid < KK * CN) {
        int c = tid >> 6, k = tid & (KK - 1);     // g_W1t[c][k]
        float s = 0.f;
        for (int i = 0; i < CN; i++) s = fmaf(lin0_w[k * CN + i], conv1_w[i * CN + c], s);
        g_W1t[tid] = s;
    } else if (tid < 2 * KK * CN) {
        int t = tid - KK * CN;
        int k = t >> 9, c = t & (CN - 1);
        float s = 0.f;
        for (int i = 0; i < CN; i++) s = fmaf(conv2_w[c * CN + i], lin1_w[i * KK + k], s);
        g_W2t[t] = s;  // stored [k][c]
    } else if (tid < 2 * KK * CN + KK) {
        int k = tid - 2 * KK * CN;
        float s = 0.f;
        for (int i = 0; i < CN; i++) s = fmaf(lin0_w[k * CN + i], conv1_b[i], s);
        g_b1[k] = s;
    } else if (tid < 2 * KK * CN + KK + 2 * CN) {
        int t = tid - (2 * KK * CN + KK);
        if (t < CN) g_bnsum[t] = 0.f;
        else        g_bnsumsq[t - CN] = 0.f;
    }
}

// ---------------- 2. attn_raw = W1 @ x + b1  (M=64, K=512, N=16384 per batch)
// Block tile: 64k x 256n, thread tile: 8k x 8n (4 f32x2 pairs). FFMA2 inner loop.
#define A_TN 256
#define A_CH 32
__global__ __launch_bounds__(256) void attn_gemm_kernel(const float* __restrict__ x) {
    __shared__ __align__(16) float xs[A_CH][A_TN];   // 32 KB
    __shared__ __align__(16) u64 wdup[A_CH][KK];     // 16 KB, duplicated pairs
    int b = blockIdx.y;
    int n0 = blockIdx.x * A_TN;
    int tid = threadIdx.x;
    int tx = tid & 31;   // n-group (8 n)
    int ty = tid >> 5;   // k-group (8 k)

    u64 acc[8][4];
#pragma unroll
    for (int i = 0; i < 8; i++)
#pragma unroll
        for (int j = 0; j < 4; j++) acc[i][j] = 0ull;

    const float* xb = x + (size_t)b * CN * NPIX;
    for (int c0 = 0; c0 < CN; c0 += A_CH) {
#pragma unroll
        for (int j = 0; j < 8; j++) {           // stage x: 2048 float4
            int i4 = tid + j * 256;
            int cc = i4 >> 6, nn4 = i4 & 63;
            *(float4*)&xs[cc][nn4 * 4] =
                *(const float4*)&xb[(size_t)(c0 + cc) * NPIX + n0 + nn4 * 4];
        }
#pragma unroll
        for (int j = 0; j < 8; j++) {           // stage duplicated weights
            int i = tid + j * 256;
            int cc = i >> 6, k = i & 63;
            float w = g_W1t[(c0 + cc) * KK + k];
            wdup[cc][k] = pack2(w, w);
        }
        __syncthreads();
#pragma unroll 8
        for (int cc = 0; cc < A_CH; cc++) {
            ulonglong2 xa = *(const ulonglong2*)&xs[cc][tx * 8];
            ulonglong2 xc = *(const ulonglong2*)&xs[cc][tx * 8 + 4];
            u64 xv[4] = {xa.x, xa.y, xc.x, xc.y};
            ulonglong2 wa = *(const ulonglong2*)&wdup[cc][ty * 8];
            ulonglong2 wb = *(const ulonglong2*)&wdup[cc][ty * 8 + 2];
            ulonglong2 wc = *(const ulonglong2*)&wdup[cc][ty * 8 + 4];
            ulonglong2 wd = *(const ulonglong2*)&wdup[cc][ty * 8 + 6];
            u64 wv[8] = {wa.x, wa.y, wb.x, wb.y, wc.x, wc.y, wd.x, wd.y};
#pragma unroll
            for (int ki = 0; ki < 8; ki++)
#pragma unroll
                for (int jp = 0; jp < 4; jp++)
                    acc[ki][jp] = ffma2(wv[ki], xv[jp], acc[ki][jp]);
        }
        __syncthreads();
    }
    // epilogue: + b1, store
#pragma unroll
    for (int ki = 0; ki < 8; ki++) {
        int k = ty * 8 + ki;
        float bb = g_b1[k];
        float2 r0 = unpack2(acc[ki][0]), r1 = unpack2(acc[ki][1]);
        float2 r2 = unpack2(acc[ki][2]), r3 = unpack2(acc[ki][3]);
        float4 o0 = {r0.x + bb, r0.y + bb, r1.x + bb, r1.y + bb};
        float4 o1 = {r2.x + bb, r2.y + bb, r3.x + bb, r3.y + bb};
        float* p = g_attn + (size_t)(b * KK + k) * NPIX + n0 + tx * 8;
        *(float4*)p = o0;
        *(float4*)(p + 4) = o1;
    }
}

// ---------------- 3. softmax over n (one block per (b,k) row of 16384) ------
__global__ __launch_bounds__(256) void softmax_kernel() {
    int row = blockIdx.x;  // b*KK + k
    float* p = g_attn + (size_t)row * NPIX;
    int tid = threadIdx.x;

    float v[64];
    float m = -1e30f;
#pragma unroll
    for (int i = 0; i < 64; i++) {
        v[i] = p[tid + (i << 8)];
        m = fmaxf(m, v[i]);
    }
    __shared__ float red[8];
#pragma unroll
    for (int o = 16; o > 0; o >>= 1) m = fmaxf(m, __shfl_xor_sync(0xffffffffu, m, o));
    if ((tid & 31) == 0) red[tid >> 5] = m;
    __syncthreads();
    if (tid < 32) {
        float t = (tid < 8) ? red[tid] : -1e30f;
#pragma unroll
        for (int o = 4; o > 0; o >>= 1) t = fmaxf(t, __shfl_xor_sync(0xffffffffu, t, o));
        if (tid == 0) red[0] = t;
    }
    __syncthreads();
    m = red[0];
    __syncthreads();

    float s = 0.f;
#pragma unroll
    for (int i = 0; i < 64; i++) {
        v[i] = __expf(v[i] - m);
        s += v[i];
    }
#pragma unroll
    for (int o = 16; o > 0; o >>= 1) s += __shfl_xor_sync(0xffffffffu, s, o);
    if ((tid & 31) == 0) red[tid >> 5] = s;
    __syncthreads();
    if (tid < 32) {
        float t = (tid < 8) ? red[tid] : 0.f;
#pragma unroll
        for (int o = 4; o > 0; o >>= 1) t += __shfl_xor_sync(0xffffffffu, t, o);
        if (tid == 0) red[0] = t;
    }
    __syncthreads();
    float inv = 1.f / red[0];
#pragma unroll
    for (int i = 0; i < 64; i++) p[tid + (i << 8)] = v[i] * inv;
}

// ---------------- 4. y3 = W2 @ (attn / (eps + colsum_k)), BN stats fused ----
// Block tile: 128c x 128n, thread tile 8c x 8n (4 f32x2 pairs). FFMA2 inner loop.
#define B_TN 128
#define B_TC 128
#define B_KCH 32
__global__ __launch_bounds__(256) void out_gemm_kernel() {
    __shared__ __align__(16) float as[B_KCH][B_TN];   // 16 KB
    __shared__ __align__(16) u64 wdup[B_KCH][B_TC];   // 32 KB (duplicated)
    __shared__ float dsum[B_TN];
    int b = blockIdx.z;
    int c0 = blockIdx.y * B_TC;
    int n0 = blockIdx.x * B_TN;
    int tid = threadIdx.x;
    int tx = tid & 15, ty = tid >> 4;

    u64 acc[8][4];
#pragma unroll
    for (int i = 0; i < 8; i++)
#pragma unroll
        for (int j = 0; j < 4; j++) acc[i][j] = 0ull;
    if (tid < B_TN) dsum[tid] = 0.f;

    const float* ab = g_attn + (size_t)b * KK * NPIX;
    for (int k0 = 0; k0 < KK; k0 += B_KCH) {
        __syncthreads();
#pragma unroll
        for (int j = 0; j < 4; j++) {           // stage attn tile: 1024 float4
            int i4 = tid + j * 256;
            int kk = i4 >> 5, nn4 = i4 & 31;
            *(float4*)&as[kk][nn4 * 4] =
                *(const float4*)&ab[(size_t)(k0 + kk) * NPIX + n0 + nn4 * 4];
        }
#pragma unroll
        for (int j = 0; j < 16; j++) {          // stage duplicated weights
            int i = tid + j * 256;
            int kk = i >> 7, cc = i & 127;
            float w = g_W2t[(k0 + kk) * CN + c0 + cc];
            wdup[kk][cc] = pack2(w, w);
        }
        __syncthreads();
        if (tid < B_TN) {  // accumulate column L1 sums from the staged tile
            float s = 0.f;
#pragma unroll
            for (int kk = 0; kk < B_KCH; kk++) s += as[kk][tid];
            dsum[tid] += s;
        }
#pragma unroll 8
        for (int kk = 0; kk < B_KCH; kk++) {
            ulonglong2 aa = *(const ulonglong2*)&as[kk][tx * 8];
            ulonglong2 ac = *(const ulonglong2*)&as[kk][tx * 8 + 4];
            u64 av[4] = {aa.x, aa.y, ac.x, ac.y};
            ulonglong2 wa = *(const ulonglong2*)&wdup[kk][ty * 8];
            ulonglong2 wb = *(const ulonglong2*)&wdup[kk][ty * 8 + 2];
            ulonglong2 wc = *(const ulonglong2*)&wdup[kk][ty * 8 + 4];
            ulonglong2 wd = *(const ulonglong2*)&wdup[kk][ty * 8 + 6];
            u64 wv[8] = {wa.x, wa.y, wb.x, wb.y, wc.x, wc.y, wd.x, wd.y};
#pragma unroll
            for (int ki = 0; ki < 8; ki++)
#pragma unroll
                for (int jp = 0; jp < 4; jp++)
                    acc[ki][jp] = ffma2(wv[ki], av[jp], acc[ki][jp]);
        }
    }
    __syncthreads();
    float inv[8];
#pragma unroll
    for (int j = 0; j < 8; j++) inv[j] = 1.f / (1e-9f + dsum[tx * 8 + j]);
#pragma unroll
    for (int ki = 0; ki < 8; ki++) {
        float2 y0 = unpack2(acc[ki][0]), y1 = unpack2(acc[ki][1]);
        float2 y2 = unpack2(acc[ki][2]), y3 = unpack2(acc[ki][3]);
        float4 o0 = {y0.x * inv[0], y0.y * inv[1], y1.x * inv[2], y1.y * inv[3]};
        float4 o1 = {y2.x * inv[4], y2.y * inv[5], y3.x * inv[6], y3.y * inv[7]};
        float* yr = g_y3 + ((size_t)(b * CN + c0 + ty * 8 + ki)) * NPIX + n0 + tx * 8;
        *(float4*)yr = o0;
        *(float4*)(yr + 4) = o1;
        // fused BN partial sums over this thread's 8 n values
        float s = o0.x + o0.y + o0.z + o0.w + o1.x + o1.y + o1.z + o1.w;
        float sq = o0.x * o0.x + o0.y * o0.y + o0.z * o0.z + o0.w * o0.w
                 + o1.x * o1.x + o1.y * o1.y + o1.z * o1.z + o1.w * o1.w;
#pragma unroll
        for (int o = 8; o > 0; o >>= 1) {       // reduce across 16 tx lanes
            s += __shfl_xor_sync(0xffffffffu, s, o);
            sq += __shfl_xor_sync(0xffffffffu, sq, o);
        }
        if (tx == 0) {
            atomicAdd(&g_bnsum[c0 + ty * 8 + ki], s);
            atomicAdd(&g_bnsumsq[c0 + ty * 8 + ki], sq);
        }
    }
}

// ---------------- 5. fold BN into per-channel scale/shift -------------------
__global__ void bnscale_kernel(const float* __restrict__ gamma,
                               const float* __restrict__ beta) {
    int c = threadIdx.x + blockIdx.x * blockDim.x;
    if (c < CN) {
        const float cnt = (float)(BB * NPIX);
        float mean = g_bnsum[c] / cnt;
        float var = g_bnsumsq[c] / cnt - mean * mean;
        float sc = gamma[c] * rsqrtf(var + BN_EPS);
        g_scale[c] = sc;
        g_shift[c] = beta[c] - mean * sc;
    }
}

// ---------------- 6. out = relu(y3*scale + shift + x) -----------------------
__global__ __launch_bounds__(256) void final_kernel(const float* __restrict__ x,
                                                    float* __restrict__ out) {
    size_t i4 = (size_t)blockIdx.x * blockDim.x + threadIdx.x;
    const size_t total4 = (size_t)BB * CN * NPIX / 4;
    if (i4 >= total4) return;
    int c = (int)((i4 >> 12) & (CN - 1));
    float sc = g_scale[c], sh = g_shift[c];
    float4 y = ((const float4*)g_y3)[i4];
    float4 xi = ((const float4*)x)[i4];
    float4 o;
    o.x = fmaxf(fmaf(y.x, sc, sh) + xi.x, 0.f);
    o.y = fmaxf(fmaf(y.y, sc, sh) + xi.y, 0.f);
    o.z = fmaxf(fmaf(y.z, sc, sh) + xi.z, 0.f);
    o.w = fmaxf(fmaf(y.w, sc, sh) + xi.w, 0.f);
    ((float4*)out)[i4] = o;
}

// ---------------- launch -----------------------------------------------------
extern "C" void kernel_launch(void* const* d_in, const int* in_sizes, int n_in,
                              void* d_out, int out_size) {
    const float* x       = (const float*)d_in[0];
    const float* conv1_w = (const float*)d_in[1];
    const float* conv1_b = (const float*)d_in[2];
    const float* lin0_w  = (const float*)d_in[3];
    const float* lin1_w  = (const float*)d_in[4];
    const float* conv2_w = (const float*)d_in[5];
    const float* gamma   = (const float*)d_in[6];
    const float* beta    = (const float*)d_in[7];
    float* out = (float*)d_out;

    prep_kernel<<<(2 * KK * CN + KK + 2 * CN + 255) / 256, 256>>>(
        conv1_w, conv1_b, lin0_w, lin1_w, conv2_w);
    attn_gemm_kernel<<<dim3(NPIX / A_TN, BB), 256>>>(x);
    softmax_kernel<<<BB * KK, 256>>>();
    out_gemm_kernel<<<dim3(NPIX / B_TN, CN / B_TC, BB), 256>>>();
    bnscale_kernel<<<2, 256>>>(gamma, beta);
    final_kernel<<<(int)(((size_t)BB * CN * NPIX / 4 + 255) / 256), 256>>>(x, out);
}

// round 5
// speedup vs baseline: 1.3279x; 1.0567x over previous
#include <cuda_runtime.h>

#define CN 512
#define KK 64
#define NPIX 16384
#define BB 8
#define BN_EPS 1e-5f

typedef unsigned long long u64;

__device__ __forceinline__ u64 ffma2(u64 a, u64 b, u64 c) {
    u64 d;
    asm("fma.rn.f32x2 %0, %1, %2, %3;" : "=l"(d) : "l"(a), "l"(b), "l"(c));
    return d;
}
__device__ __forceinline__ u64 pack2(float x, float y) {
    u64 v; asm("mov.b64 %0, {%1, %2};" : "=l"(v) : "f"(x), "f"(y)); return v;
}
__device__ __forceinline__ float2 unpack2(u64 v) {
    float2 f; asm("mov.b64 {%0, %1}, %2;" : "=f"(f.x), "=f"(f.y) : "l"(v)); return f;
}

// ---------------- scratch (static device globals; no allocation) -------------
__device__ float g_W1t[CN * KK];         // (lin0_w @ conv1_w)^T  [c][k]
__device__ float g_b1[KK];               // lin0_w @ conv1_b
__device__ float g_W2t[KK * CN];         // (conv2_w @ lin1_w)^T  [k][c]
__device__ float g_attn[(size_t)BB * KK * NPIX];        // 32 MB
__device__ float g_y3[(size_t)BB * CN * NPIX];          // 256 MB
__device__ float g_bnsum[CN];
__device__ float g_bnsumsq[CN];
__device__ float g_scale[CN];
__device__ float g_shift[CN];

// ---------------- 1. precompute folded weights + zero BN accumulators -------
__global__ void prep_kernel(const float* __restrict__ conv1_w,
                            const float* __restrict__ conv1_b,
                            const float* __restrict__ lin0_w,
                            const float* __restrict__ lin1_w,
                            const float* __restrict__ conv2_w) {
    int tid = blockIdx.x * blockDim.x + threadIdx.x;
    if (tid < KK * CN) {
        int c = tid >> 6, k = tid & (KK - 1);     // g_W1t[c][k]
        float s = 0.f;
        for (int i = 0; i < CN; i++) s = fmaf(lin0_w[k * CN + i], conv1_w[i * CN + c], s);
        g_W1t[tid] = s;
    } else if (tid < 2 * KK * CN) {
        int t = tid - KK * CN;
        int k = t >> 9, c = t & (CN - 1);
        float s = 0.f;
        for (int i = 0; i < CN; i++) s = fmaf(conv2_w[c * CN + i], lin1_w[i * KK + k], s);
        g_W2t[t] = s;  // stored [k][c]
    } else if (tid < 2 * KK * CN + KK) {
        int k = tid - 2 * KK * CN;
        float s = 0.f;
        for (int i = 0; i < CN; i++) s = fmaf(lin0_w[k * CN + i], conv1_b[i], s);
        g_b1[k] = s;
    } else if (tid < 2 * KK * CN + KK + 2 * CN) {
        int t = tid - (2 * KK * CN + KK);
        if (t < CN) g_bnsum[t] = 0.f;
        else        g_bnsumsq[t - CN] = 0.f;
    }
}

// ---------------- 2. attn_raw = W1 @ x + b1  (M=64, K=512, N=16384 per batch)
// Block tile: 64k x 256n, thread tile: 8k x 8n. Non-dup weights, reg-dup FFMA2.
#define A_TN 256
#define A_CH 32
__global__ __launch_bounds__(256) void attn_gemm_kernel(const float* __restrict__ x) {
    __shared__ __align__(16) float xs[A_CH][A_TN];   // 32 KB
    __shared__ __align__(16) float ws[A_CH][KK];     // 8 KB (plain floats)
    int b = blockIdx.y;
    int n0 = blockIdx.x * A_TN;
    int tid = threadIdx.x;
    int tx = tid & 31;   // n-group (8 n)   -- whole warp shares one ty
    int ty = tid >> 5;   // k-group (8 k)

    u64 acc[8][4];
#pragma unroll
    for (int i = 0; i < 8; i++)
#pragma unroll
        for (int j = 0; j < 4; j++) acc[i][j] = 0ull;

    const float* xb = x + (size_t)b * CN * NPIX;
    for (int c0 = 0; c0 < CN; c0 += A_CH) {
#pragma unroll
        for (int j = 0; j < 8; j++) {           // stage x: 2048 float4
            int i4 = tid + j * 256;
            int cc = i4 >> 6, nn4 = i4 & 63;
            *(float4*)&xs[cc][nn4 * 4] =
                *(const float4*)&xb[(size_t)(c0 + cc) * NPIX + n0 + nn4 * 4];
        }
#pragma unroll
        for (int j = 0; j < 2; j++) {           // stage weights: 512 float4
            int i4 = tid + j * 256;
            int cc = i4 >> 4, k4 = i4 & 15;
            *(float4*)&ws[cc][k4 * 4] =
                *(const float4*)&g_W1t[(c0 + cc) * KK + k4 * 4];
        }
        __syncthreads();
#pragma unroll 8
        for (int cc = 0; cc < A_CH; cc++) {
            ulonglong2 xa = *(const ulonglong2*)&xs[cc][tx * 8];
            ulonglong2 xc = *(const ulonglong2*)&xs[cc][tx * 8 + 4];
            u64 xv[4] = {xa.x, xa.y, xc.x, xc.y};
            float4 w0 = *(const float4*)&ws[cc][ty * 8];      // uniform across warp
            float4 w1 = *(const float4*)&ws[cc][ty * 8 + 4];
            u64 wv[8] = {pack2(w0.x, w0.x), pack2(w0.y, w0.y),
                         pack2(w0.z, w0.z), pack2(w0.w, w0.w),
                         pack2(w1.x, w1.x), pack2(w1.y, w1.y),
                         pack2(w1.z, w1.z), pack2(w1.w, w1.w)};
#pragma unroll
            for (int ki = 0; ki < 8; ki++)
#pragma unroll
                for (int jp = 0; jp < 4; jp++)
                    acc[ki][jp] = ffma2(wv[ki], xv[jp], acc[ki][jp]);
        }
        __syncthreads();
    }
    // epilogue: + b1, store
#pragma unroll
    for (int ki = 0; ki < 8; ki++) {
        int k = ty * 8 + ki;
        float bb = g_b1[k];
        float2 r0 = unpack2(acc[ki][0]), r1 = unpack2(acc[ki][1]);
        float2 r2 = unpack2(acc[ki][2]), r3 = unpack2(acc[ki][3]);
        float4 o0 = {r0.x + bb, r0.y + bb, r1.x + bb, r1.y + bb};
        float4 o1 = {r2.x + bb, r2.y + bb, r3.x + bb, r3.y + bb};
        float* p = g_attn + (size_t)(b * KK + k) * NPIX + n0 + tx * 8;
        *(float4*)p = o0;
        *(float4*)(p + 4) = o1;
    }
}

// ---------------- 3. softmax over n (one block per (b,k) row of 16384) ------
__global__ __launch_bounds__(256) void softmax_kernel() {
    int row = blockIdx.x;  // b*KK + k
    float* p = g_attn + (size_t)row * NPIX;
    int tid = threadIdx.x;

    float v[64];
    float m = -1e30f;
#pragma unroll
    for (int i = 0; i < 64; i++) {
        v[i] = p[tid + (i << 8)];
        m = fmaxf(m, v[i]);
    }
    __shared__ float red[8];
#pragma unroll
    for (int o = 16; o > 0; o >>= 1) m = fmaxf(m, __shfl_xor_sync(0xffffffffu, m, o));
    if ((tid & 31) == 0) red[tid >> 5] = m;
    __syncthreads();
    if (tid < 32) {
        float t = (tid < 8) ? red[tid] : -1e30f;
#pragma unroll
        for (int o = 4; o > 0; o >>= 1) t = fmaxf(t, __shfl_xor_sync(0xffffffffu, t, o));
        if (tid == 0) red[0] = t;
    }
    __syncthreads();
    m = red[0];
    __syncthreads();

    float s = 0.f;
#pragma unroll
    for (int i = 0; i < 64; i++) {
        v[i] = __expf(v[i] - m);
        s += v[i];
    }
#pragma unroll
    for (int o = 16; o > 0; o >>= 1) s += __shfl_xor_sync(0xffffffffu, s, o);
    if ((tid & 31) == 0) red[tid >> 5] = s;
    __syncthreads();
    if (tid < 32) {
        float t = (tid < 8) ? red[tid] : 0.f;
#pragma unroll
        for (int o = 4; o > 0; o >>= 1) t += __shfl_xor_sync(0xffffffffu, t, o);
        if (tid == 0) red[0] = t;
    }
    __syncthreads();
    float inv = 1.f / red[0];
#pragma unroll
    for (int i = 0; i < 64; i++) p[tid + (i << 8)] = v[i] * inv;
}

// ---------------- 4. y3 = W2 @ (attn / (eps + colsum_k)), BN stats fused ----
// Block tile: 128c x 128n, thread tile 8c x 8n. Non-dup weights, reg-dup FFMA2.
#define B_TN 128
#define B_TC 128
#define B_KCH 32
__global__ __launch_bounds__(256) void out_gemm_kernel() {
    __shared__ __align__(16) float as[B_KCH][B_TN];   // 16 KB
    __shared__ __align__(16) float ws[B_KCH][B_TC];   // 16 KB (plain floats)
    __shared__ float dsum[B_TN];
    int b = blockIdx.z;
    int c0 = blockIdx.y * B_TC;
    int n0 = blockIdx.x * B_TN;
    int tid = threadIdx.x;
    int tx = tid & 15, ty = tid >> 4;

    u64 acc[8][4];
#pragma unroll
    for (int i = 0; i < 8; i++)
#pragma unroll
        for (int j = 0; j < 4; j++) acc[i][j] = 0ull;
    if (tid < B_TN) dsum[tid] = 0.f;

    const float* ab = g_attn + (size_t)b * KK * NPIX;
    for (int k0 = 0; k0 < KK; k0 += B_KCH) {
        __syncthreads();
#pragma unroll
        for (int j = 0; j < 4; j++) {           // stage attn tile: 1024 float4
            int i4 = tid + j * 256;
            int kk = i4 >> 5, nn4 = i4 & 31;
            *(float4*)&as[kk][nn4 * 4] =
                *(const float4*)&ab[(size_t)(k0 + kk) * NPIX + n0 + nn4 * 4];
        }
#pragma unroll
        for (int j = 0; j < 4; j++) {           // stage weights: 1024 float4
            int i4 = tid + j * 256;
            int kk = i4 >> 5, cc4 = i4 & 31;
            *(float4*)&ws[kk][cc4 * 4] =
                *(const float4*)&g_W2t[(k0 + kk) * CN + c0 + cc4 * 4];
        }
        __syncthreads();
        if (tid < B_TN) {  // accumulate column L1 sums from the staged tile
            float s = 0.f;
#pragma unroll
            for (int kk = 0; kk < B_KCH; kk++) s += as[kk][tid];
            dsum[tid] += s;
        }
#pragma unroll 8
        for (int kk = 0; kk < B_KCH; kk++) {
            ulonglong2 aa = *(const ulonglong2*)&as[kk][tx * 8];
            ulonglong2 ac = *(const ulonglong2*)&as[kk][tx * 8 + 4];
            u64 av[4] = {aa.x, aa.y, ac.x, ac.y};
            float4 w0 = *(const float4*)&ws[kk][ty * 8];
            float4 w1 = *(const float4*)&ws[kk][ty * 8 + 4];
            u64 wv[8] = {pack2(w0.x, w0.x), pack2(w0.y, w0.y),
                         pack2(w0.z, w0.z), pack2(w0.w, w0.w),
                         pack2(w1.x, w1.x), pack2(w1.y, w1.y),
                         pack2(w1.z, w1.z), pack2(w1.w, w1.w)};
#pragma unroll
            for (int ki = 0; ki < 8; ki++)
#pragma unroll
                for (int jp = 0; jp < 4; jp++)
                    acc[ki][jp] = ffma2(wv[ki], av[jp], acc[ki][jp]);
        }
    }
    __syncthreads();
    float inv[8];
#pragma unroll
    for (int j = 0; j < 8; j++) inv[j] = 1.f / (1e-9f + dsum[tx * 8 + j]);
#pragma unroll
    for (int ki = 0; ki < 8; ki++) {
        float2 y0 = unpack2(acc[ki][0]), y1 = unpack2(acc[ki][1]);
        float2 y2 = unpack2(acc[ki][2]), y3 = unpack2(acc[ki][3]);
        float4 o0 = {y0.x * inv[0], y0.y * inv[1], y1.x * inv[2], y1.y * inv[3]};
        float4 o1 = {y2.x * inv[4], y2.y * inv[5], y3.x * inv[6], y3.y * inv[7]};
        float* yr = g_y3 + ((size_t)(b * CN + c0 + ty * 8 + ki)) * NPIX + n0 + tx * 8;
        *(float4*)yr = o0;
        *(float4*)(yr + 4) = o1;
        // fused BN partial sums over this thread's 8 n values
        float s = o0.x + o0.y + o0.z + o0.w + o1.x + o1.y + o1.z + o1.w;
        float sq = o0.x * o0.x + o0.y * o0.y + o0.z * o0.z + o0.w * o0.w
                 + o1.x * o1.x + o1.y * o1.y + o1.z * o1.z + o1.w * o1.w;
#pragma unroll
        for (int o = 8; o > 0; o >>= 1) {       // reduce across 16 tx lanes
            s += __shfl_xor_sync(0xffffffffu, s, o);
            sq += __shfl_xor_sync(0xffffffffu, sq, o);
        }
        if (tx == 0) {
            atomicAdd(&g_bnsum[c0 + ty * 8 + ki], s);
            atomicAdd(&g_bnsumsq[c0 + ty * 8 + ki], sq);
        }
    }
}

// ---------------- 5. fold BN into per-channel scale/shift -------------------
__global__ void bnscale_kernel(const float* __restrict__ gamma,
                               const float* __restrict__ beta) {
    int c = threadIdx.x + blockIdx.x * blockDim.x;
    if (c < CN) {
        const float cnt = (float)(BB * NPIX);
        float mean = g_bnsum[c] / cnt;
        float var = g_bnsumsq[c] / cnt - mean * mean;
        float sc = gamma[c] * rsqrtf(var + BN_EPS);
        g_scale[c] = sc;
        g_shift[c] = beta[c] - mean * sc;
    }
}

// ---------------- 6. out = relu(y3*scale + shift + x) -----------------------
__global__ __launch_bounds__(256) void final_kernel(const float* __restrict__ x,
                                                    float* __restrict__ out) {
    size_t i4 = (size_t)blockIdx.x * blockDim.x + threadIdx.x;
    const size_t total4 = (size_t)BB * CN * NPIX / 4;
    if (i4 >= total4) return;
    int c = (int)((i4 >> 12) & (CN - 1));
    float sc = g_scale[c], sh = g_shift[c];
    float4 y = ((const float4*)g_y3)[i4];
    float4 xi = ((const float4*)x)[i4];
    float4 o;
    o.x = fmaxf(fmaf(y.x, sc, sh) + xi.x, 0.f);
    o.y = fmaxf(fmaf(y.y, sc, sh) + xi.y, 0.f);
    o.z = fmaxf(fmaf(y.z, sc, sh) + xi.z, 0.f);
    o.w = fmaxf(fmaf(y.w, sc, sh) + xi.w, 0.f);
    ((float4*)out)[i4] = o;
}

// ---------------- launch -----------------------------------------------------
extern "C" void kernel_launch(void* const* d_in, const int* in_sizes, int n_in,
                              void* d_out, int out_size) {
    const float* x       = (const float*)d_in[0];
    const float* conv1_w = (const float*)d_in[1];
    const float* conv1_b = (const float*)d_in[2];
    const float* lin0_w  = (const float*)d_in[3];
    const float* lin1_w  = (const float*)d_in[4];
    const float* conv2_w = (const float*)d_in[5];
    const float* gamma   = (const float*)d_in[6];
    const float* beta    = (const float*)d_in[7];
    float* out = (float*)d_out;

    prep_kernel<<<(2 * KK * CN + KK + 2 * CN + 255) / 256, 256>>>(
        conv1_w, conv1_b, lin0_w, lin1_w, conv2_w);
    attn_gemm_kernel<<<dim3(NPIX / A_TN, BB), 256>>>(x);
    softmax_kernel<<<BB * KK, 256>>>();
    out_gemm_kernel<<<dim3(NPIX / B_TN, CN / B_TC, BB), 256>>>();
    bnscale_kernel<<<2, 256>>>(gamma, beta);
    final_kernel<<<(int)(((size_t)BB * CN * NPIX / 4 + 255) / 256), 256>>>(x, out);
}

// round 6
// speedup vs baseline: 1.4670x; 1.1048x over previous
#include <cuda_runtime.h>

#define CN 512
#define KK 64
#define NPIX 16384
#define BB 8
#define BN_EPS 1e-5f

typedef unsigned long long u64;

__device__ __forceinline__ u64 ffma2(u64 a, u64 b, u64 c) {
    u64 d;
    asm("fma.rn.f32x2 %0, %1, %2, %3;" : "=l"(d) : "l"(a), "l"(b), "l"(c));
    return d;
}
__device__ __forceinline__ u64 pack2(float x, float y) {
    u64 v; asm("mov.b64 %0, {%1, %2};" : "=l"(v) : "f"(x), "f"(y)); return v;
}
__device__ __forceinline__ float2 unpack2(u64 v) {
    float2 f; asm("mov.b64 {%0, %1}, %2;" : "=f"(f.x), "=f"(f.y) : "l"(v)); return f;
}
__device__ __forceinline__ void cp16(void* smem_dst, const void* gmem_src) {
    unsigned s = (unsigned)__cvta_generic_to_shared(smem_dst);
    asm volatile("cp.async.cg.shared.global [%0], [%1], 16;" :: "r"(s), "l"(gmem_src));
}
#define CP_COMMIT asm volatile("cp.async.commit_group;")
#define CP_WAIT0  asm volatile("cp.async.wait_group 0;")
#define CP_WAIT1  asm volatile("cp.async.wait_group 1;")

// ---------------- scratch (static device globals; no allocation) -------------
__device__ float g_W1t[CN * KK];         // (lin0_w @ conv1_w)^T  [c][k]
__device__ float g_b1[KK];               // lin0_w @ conv1_b
__device__ float g_W2t[KK * CN];         // (conv2_w @ lin1_w)^T  [k][c]
__device__ float g_attn[(size_t)BB * KK * NPIX];        // 32 MB
__device__ float g_y3[(size_t)BB * CN * NPIX];          // 256 MB
__device__ float g_bnsum[CN];
__device__ float g_bnsumsq[CN];
__device__ float g_scale[CN];
__device__ float g_shift[CN];

// ---------------- 1. precompute folded weights + zero BN accumulators -------
__global__ void prep_kernel(const float* __restrict__ conv1_w,
                            const float* __restrict__ conv1_b,
                            const float* __restrict__ lin0_w,
                            const float* __restrict__ lin1_w,
                            const float* __restrict__ conv2_w) {
    int tid = blockIdx.x * blockDim.x + threadIdx.x;
    if (tid < KK * CN) {
        int c = tid >> 6, k = tid & (KK - 1);     // g_W1t[c][k]
        float s = 0.f;
        for (int i = 0; i < CN; i++) s = fmaf(lin0_w[k * CN + i], conv1_w[i * CN + c], s);
        g_W1t[tid] = s;
    } else if (tid < 2 * KK * CN) {
        int t = tid - KK * CN;
        int k = t >> 9, c = t & (CN - 1);
        float s = 0.f;
        for (int i = 0; i < CN; i++) s = fmaf(conv2_w[c * CN + i], lin1_w[i * KK + k], s);
        g_W2t[t] = s;  // stored [k][c]
    } else if (tid < 2 * KK * CN + KK) {
        int k = tid - 2 * KK * CN;
        float s = 0.f;
        for (int i = 0; i < CN; i++) s = fmaf(lin0_w[k * CN + i], conv1_b[i], s);
        g_b1[k] = s;
    } else if (tid < 2 * KK * CN + KK + 2 * CN) {
        int t = tid - (2 * KK * CN + KK);
        if (t < CN) g_bnsum[t] = 0.f;
        else        g_bnsumsq[t - CN] = 0.f;
    }
}

// ---------------- 2. attn_raw = W1 @ x + b1  (M=64, K=512, N=16384 per batch)
// 64k x 256n block tile, 8k x 8n thread tile, cp.async double-buffered chunks.
#define A_TN 256
#define A_CH 32
#define A_NC (CN / A_CH)          // 16 chunks
#define A_SMEM (2 * A_CH * A_TN * 4 + 2 * A_CH * KK * 4)   // 64KB + 16KB = 80KB
__global__ __launch_bounds__(256) void attn_gemm_kernel(const float* __restrict__ x) {
    extern __shared__ __align__(16) char sm_a[];
    float (*xs)[A_CH][A_TN] = (float (*)[A_CH][A_TN])sm_a;
    float (*ws)[A_CH][KK]   = (float (*)[A_CH][KK])(sm_a + 2 * A_CH * A_TN * 4);

    int b = blockIdx.y;
    int n0 = blockIdx.x * A_TN;
    int tid = threadIdx.x;
    int tx = tid & 31;   // n-group (8 n)
    int ty = tid >> 5;   // k-group (8 k)
    const float* xb = x + (size_t)b * CN * NPIX;

    u64 acc[8][4];
#pragma unroll
    for (int i = 0; i < 8; i++)
#pragma unroll
        for (int j = 0; j < 4; j++) acc[i][j] = 0ull;

    // stage chunk `ch` into buffer `bf`
    auto stage = [&](int ch, int bf) {
        int c0 = ch * A_CH;
#pragma unroll
        for (int j = 0; j < 8; j++) {           // x tile: 2048 float4
            int i4 = tid + j * 256;
            int cc = i4 >> 6, nn4 = i4 & 63;
            cp16(&xs[bf][cc][nn4 * 4], &xb[(size_t)(c0 + cc) * NPIX + n0 + nn4 * 4]);
        }
#pragma unroll
        for (int j = 0; j < 2; j++) {           // w tile: 512 float4
            int i4 = tid + j * 256;
            int cc = i4 >> 4, k4 = i4 & 15;
            cp16(&ws[bf][cc][k4 * 4], &g_W1t[(c0 + cc) * KK + k4 * 4]);
        }
    };

    stage(0, 0);
    CP_COMMIT;
    for (int ch = 0; ch < A_NC; ch++) {
        int cur = ch & 1;
        if (ch + 1 < A_NC) { stage(ch + 1, cur ^ 1); CP_COMMIT; CP_WAIT1; }
        else               { CP_WAIT0; }
        __syncthreads();
#pragma unroll 8
        for (int cc = 0; cc < A_CH; cc++) {
            ulonglong2 xa = *(const ulonglong2*)&xs[cur][cc][tx * 8];
            ulonglong2 xc = *(const ulonglong2*)&xs[cur][cc][tx * 8 + 4];
            u64 xv[4] = {xa.x, xa.y, xc.x, xc.y};
            float4 w0 = *(const float4*)&ws[cur][cc][ty * 8];
            float4 w1 = *(const float4*)&ws[cur][cc][ty * 8 + 4];
            u64 wv[8] = {pack2(w0.x, w0.x), pack2(w0.y, w0.y),
                         pack2(w0.z, w0.z), pack2(w0.w, w0.w),
                         pack2(w1.x, w1.x), pack2(w1.y, w1.y),
                         pack2(w1.z, w1.z), pack2(w1.w, w1.w)};
#pragma unroll
            for (int ki = 0; ki < 8; ki++)
#pragma unroll
                for (int jp = 0; jp < 4; jp++)
                    acc[ki][jp] = ffma2(wv[ki], xv[jp], acc[ki][jp]);
        }
        __syncthreads();
    }
    // epilogue: + b1, store
#pragma unroll
    for (int ki = 0; ki < 8; ki++) {
        int k = ty * 8 + ki;
        float bb = g_b1[k];
        float2 r0 = unpack2(acc[ki][0]), r1 = unpack2(acc[ki][1]);
        float2 r2 = unpack2(acc[ki][2]), r3 = unpack2(acc[ki][3]);
        float4 o0 = {r0.x + bb, r0.y + bb, r1.x + bb, r1.y + bb};
        float4 o1 = {r2.x + bb, r2.y + bb, r3.x + bb, r3.y + bb};
        float* p = g_attn + (size_t)(b * KK + k) * NPIX + n0 + tx * 8;
        *(float4*)p = o0;
        *(float4*)(p + 4) = o1;
    }
}

// ---------------- 3. softmax over n (one block per (b,k) row of 16384) ------
__global__ __launch_bounds__(256) void softmax_kernel() {
    int row = blockIdx.x;  // b*KK + k
    float* p = g_attn + (size_t)row * NPIX;
    int tid = threadIdx.x;

    float v[64];
    float m = -1e30f;
#pragma unroll
    for (int i = 0; i < 64; i++) {
        v[i] = p[tid + (i << 8)];
        m = fmaxf(m, v[i]);
    }
    __shared__ float red[8];
#pragma unroll
    for (int o = 16; o > 0; o >>= 1) m = fmaxf(m, __shfl_xor_sync(0xffffffffu, m, o));
    if ((tid & 31) == 0) red[tid >> 5] = m;
    __syncthreads();
    if (tid < 32) {
        float t = (tid < 8) ? red[tid] : -1e30f;
#pragma unroll
        for (int o = 4; o > 0; o >>= 1) t = fmaxf(t, __shfl_xor_sync(0xffffffffu, t, o));
        if (tid == 0) red[0] = t;
    }
    __syncthreads();
    m = red[0];
    __syncthreads();

    float s = 0.f;
#pragma unroll
    for (int i = 0; i < 64; i++) {
        v[i] = __expf(v[i] - m);
        s += v[i];
    }
#pragma unroll
    for (int o = 16; o > 0; o >>= 1) s += __shfl_xor_sync(0xffffffffu, s, o);
    if ((tid & 31) == 0) red[tid >> 5] = s;
    __syncthreads();
    if (tid < 32) {
        float t = (tid < 8) ? red[tid] : 0.f;
#pragma unroll
        for (int o = 4; o > 0; o >>= 1) t += __shfl_xor_sync(0xffffffffu, t, o);
        if (tid == 0) red[0] = t;
    }
    __syncthreads();
    float inv = 1.f / red[0];
#pragma unroll
    for (int i = 0; i < 64; i++) p[tid + (i << 8)] = v[i] * inv;
}

// ---------------- 4. y3 = W2 @ (attn / (eps + colsum_k)), BN stats fused ----
// Full K=64 attn tile resident; loop 4 weight sub-tiles of 128 c.
#define B_TN 128
#define B_TC 128
#define B_SMEM (KK * B_TN * 4 + KK * B_TC * 4 + B_TN * 4)   // 32K + 32K + 512
__global__ __launch_bounds__(256) void out_gemm_kernel() {
    extern __shared__ __align__(16) char sm_b[];
    float (*as)[B_TN] = (float (*)[B_TN])sm_b;                       // [KK][128]
    float (*ws)[B_TC] = (float (*)[B_TC])(sm_b + KK * B_TN * 4);     // [KK][128]
    float* dsum       = (float*)(sm_b + KK * B_TN * 4 + KK * B_TC * 4);

    int b = blockIdx.y;
    int n0 = blockIdx.x * B_TN;
    int tid = threadIdx.x;
    int tx = tid & 15, ty = tid >> 4;
    const float* ab = g_attn + (size_t)b * KK * NPIX;

    // stage full attn tile (KK x 128 = 2048 float4) + first weight tile
#pragma unroll
    for (int j = 0; j < 8; j++) {
        int i4 = tid + j * 256;
        int kk = i4 >> 5, nn4 = i4 & 31;
        cp16(&as[kk][nn4 * 4], &ab[(size_t)kk * NPIX + n0 + nn4 * 4]);
    }
#pragma unroll
    for (int j = 0; j < 8; j++) {
        int i4 = tid + j * 256;
        int kk = i4 >> 5, cc4 = i4 & 31;
        cp16(&ws[kk][cc4 * 4], &g_W2t[kk * CN + cc4 * 4]);
    }
    CP_COMMIT;
    CP_WAIT0;
    __syncthreads();

    // column L1 sums (once — full K resident)
    if (tid < B_TN) {
        float s = 0.f;
#pragma unroll
        for (int kk = 0; kk < KK; kk++) s += as[kk][tid];
        dsum[tid] = s;
    }
    __syncthreads();
    float inv[8];
#pragma unroll
    for (int j = 0; j < 8; j++) inv[j] = 1.f / (1e-9f + dsum[tx * 8 + j]);

    for (int cb = 0; cb < CN / B_TC; cb++) {
        if (cb) {   // stage weight sub-tile cb
            __syncthreads();
#pragma unroll
            for (int j = 0; j < 8; j++) {
                int i4 = tid + j * 256;
                int kk = i4 >> 5, cc4 = i4 & 31;
                cp16(&ws[kk][cc4 * 4], &g_W2t[kk * CN + cb * B_TC + cc4 * 4]);
            }
            CP_COMMIT;
            CP_WAIT0;
            __syncthreads();
        }
        u64 acc[8][4];
#pragma unroll
        for (int i = 0; i < 8; i++)
#pragma unroll
            for (int j = 0; j < 4; j++) acc[i][j] = 0ull;
#pragma unroll 8
        for (int kk = 0; kk < KK; kk++) {
            ulonglong2 aa = *(const ulonglong2*)&as[kk][tx * 8];
            ulonglong2 ac = *(const ulonglong2*)&as[kk][tx * 8 + 4];
            u64 av[4] = {aa.x, aa.y, ac.x, ac.y};
            float4 w0 = *(const float4*)&ws[kk][ty * 8];
            float4 w1 = *(const float4*)&ws[kk][ty * 8 + 4];
            u64 wv[8] = {pack2(w0.x, w0.x), pack2(w0.y, w0.y),
                         pack2(w0.z, w0.z), pack2(w0.w, w0.w),
                         pack2(w1.x, w1.x), pack2(w1.y, w1.y),
                         pack2(w1.z, w1.z), pack2(w1.w, w1.w)};
#pragma unroll
            for (int ki = 0; ki < 8; ki++)
#pragma unroll
                for (int jp = 0; jp < 4; jp++)
                    acc[ki][jp] = ffma2(wv[ki], av[jp], acc[ki][jp]);
        }
        // epilogue for this c sub-tile
        int c0 = cb * B_TC;
#pragma unroll
        for (int ki = 0; ki < 8; ki++) {
            float2 y0 = unpack2(acc[ki][0]), y1 = unpack2(acc[ki][1]);
            float2 y2 = unpack2(acc[ki][2]), y3 = unpack2(acc[ki][3]);
            float4 o0 = {y0.x * inv[0], y0.y * inv[1], y1.x * inv[2], y1.y * inv[3]};
            float4 o1 = {y2.x * inv[4], y2.y * inv[5], y3.x * inv[6], y3.y * inv[7]};
            float* yr = g_y3 + ((size_t)(b * CN + c0 + ty * 8 + ki)) * NPIX + n0 + tx * 8;
            *(float4*)yr = o0;
            *(float4*)(yr + 4) = o1;
            float s = o0.x + o0.y + o0.z + o0.w + o1.x + o1.y + o1.z + o1.w;
            float sq = o0.x * o0.x + o0.y * o0.y + o0.z * o0.z + o0.w * o0.w
                     + o1.x * o1.x + o1.y * o1.y + o1.z * o1.z + o1.w * o1.w;
#pragma unroll
            for (int o = 8; o > 0; o >>= 1) {
                s += __shfl_xor_sync(0xffffffffu, s, o);
                sq += __shfl_xor_sync(0xffffffffu, sq, o);
            }
            if (tx == 0) {
                atomicAdd(&g_bnsum[c0 + ty * 8 + ki], s);
                atomicAdd(&g_bnsumsq[c0 + ty * 8 + ki], sq);
            }
        }
    }
}

// ---------------- 5. fold BN into per-channel scale/shift -------------------
__global__ void bnscale_kernel(const float* __restrict__ gamma,
                               const float* __restrict__ beta) {
    int c = threadIdx.x + blockIdx.x * blockDim.x;
    if (c < CN) {
        const float cnt = (float)(BB * NPIX);
        float mean = g_bnsum[c] / cnt;
        float var = g_bnsumsq[c] / cnt - mean * mean;
        float sc = gamma[c] * rsqrtf(var + BN_EPS);
        g_scale[c] = sc;
        g_shift[c] = beta[c] - mean * sc;
    }
}

// ---------------- 6. out = relu(y3*scale + shift + x) -----------------------
__global__ __launch_bounds__(256) void final_kernel(const float* __restrict__ x,
                                                    float* __restrict__ out) {
    size_t i4 = (size_t)blockIdx.x * blockDim.x + threadIdx.x;
    const size_t total4 = (size_t)BB * CN * NPIX / 4;
    if (i4 >= total4) return;
    int c = (int)((i4 >> 12) & (CN - 1));
    float sc = g_scale[c], sh = g_shift[c];
    float4 y = ((const float4*)g_y3)[i4];
    float4 xi = ((const float4*)x)[i4];
    float4 o;
    o.x = fmaxf(fmaf(y.x, sc, sh) + xi.x, 0.f);
    o.y = fmaxf(fmaf(y.y, sc, sh) + xi.y, 0.f);
    o.z = fmaxf(fmaf(y.z, sc, sh) + xi.z, 0.f);
    o.w = fmaxf(fmaf(y.w, sc, sh) + xi.w, 0.f);
    ((float4*)out)[i4] = o;
}

// ---------------- launch -----------------------------------------------------
extern "C" void kernel_launch(void* const* d_in, const int* in_sizes, int n_in,
                              void* d_out, int out_size) {
    const float* x       = (const float*)d_in[0];
    const float* conv1_w = (const float*)d_in[1];
    const float* conv1_b = (const float*)d_in[2];
    const float* lin0_w  = (const float*)d_in[3];
    const float* lin1_w  = (const float*)d_in[4];
    const float* conv2_w = (const float*)d_in[5];
    const float* gamma   = (const float*)d_in[6];
    const float* beta    = (const float*)d_in[7];
    float* out = (float*)d_out;

    cudaFuncSetAttribute(attn_gemm_kernel,
                         cudaFuncAttributeMaxDynamicSharedMemorySize, A_SMEM);
    cudaFuncSetAttribute(out_gemm_kernel,
                         cudaFuncAttributeMaxDynamicSharedMemorySize, B_SMEM);

    prep_kernel<<<(2 * KK * CN + KK + 2 * CN + 255) / 256, 256>>>(
        conv1_w, conv1_b, lin0_w, lin1_w, conv2_w);
    attn_gemm_kernel<<<dim3(NPIX / A_TN, BB), 256, A_SMEM>>>(x);
    softmax_kernel<<<BB * KK, 256>>>();
    out_gemm_kernel<<<dim3(NPIX / B_TN, BB), 256, B_SMEM>>>();
    bnscale_kernel<<<2, 256>>>(gamma, beta);
    final_kernel<<<(int)(((size_t)BB * CN * NPIX / 4 + 255) / 256), 256>>>(x, out);
}

// round 8
// speedup vs baseline: 1.5085x; 1.0282x over previous
#include <cuda_runtime.h>

#define CN 512
#define KK 64
#define NPIX 16384
#define BB 8
#define BN_EPS 1e-5f
#define CNT ((float)(BB * NPIX))

typedef unsigned long long u64;

__device__ __forceinline__ u64 ffma2(u64 a, u64 b, u64 c) {
    u64 d;
    asm("fma.rn.f32x2 %0, %1, %2, %3;" : "=l"(d) : "l"(a), "l"(b), "l"(c));
    return d;
}
__device__ __forceinline__ u64 pack2(float x, float y) {
    u64 v; asm("mov.b64 %0, {%1, %2};" : "=l"(v) : "f"(x), "f"(y)); return v;
}
__device__ __forceinline__ float2 unpack2(u64 v) {
    float2 f; asm("mov.b64 {%0, %1}, %2;" : "=f"(f.x), "=f"(f.y) : "l"(v)); return f;
}
__device__ __forceinline__ void cp16(void* smem_dst, const void* gmem_src) {
    unsigned s = (unsigned)__cvta_generic_to_shared(smem_dst);
    asm volatile("cp.async.cg.shared.global [%0], [%1], 16;" :: "r"(s), "l"(gmem_src));
}
#define CP_COMMIT asm volatile("cp.async.commit_group;")
#define CP_WAIT0  asm volatile("cp.async.wait_group 0;")
#define CP_WAIT1  asm volatile("cp.async.wait_group 1;")

// ---------------- scratch (static device globals; no allocation) -------------
__device__ float g_W1t[CN * KK];         // (lin0_w @ conv1_w)^T  [c][k]
__device__ float g_b1[KK];               // lin0_w @ conv1_b
__device__ float g_W2t[KK * CN];         // (conv2_w @ lin1_w)^T  [k][c]
__device__ float g_attn[(size_t)BB * KK * NPIX];        // 32 MB
__device__ float g_M[KK * KK];           // sum_b  A~ A~^T   (renormalized attn)
__device__ float g_r[KK];                // sum_{b,n} A~
__device__ float g_scale[CN];
__device__ float g_shift[CN];

// ---------------- 1. precompute folded weights + zero stat accumulators -----
__global__ void prep_kernel(const float* __restrict__ conv1_w,
                            const float* __restrict__ conv1_b,
                            const float* __restrict__ lin0_w,
                            const float* __restrict__ lin1_w,
                            const float* __restrict__ conv2_w) {
    int tid = blockIdx.x * blockDim.x + threadIdx.x;
    if (tid < KK * CN) {
        int c = tid >> 6, k = tid & (KK - 1);     // g_W1t[c][k]
        float s = 0.f;
        for (int i = 0; i < CN; i++) s = fmaf(lin0_w[k * CN + i], conv1_w[i * CN + c], s);
        g_W1t[tid] = s;
    } else if (tid < 2 * KK * CN) {
        int t = tid - KK * CN;
        int k = t >> 9, c = t & (CN - 1);
        float s = 0.f;
        for (int i = 0; i < CN; i++) s = fmaf(conv2_w[c * CN + i], lin1_w[i * KK + k], s);
        g_W2t[t] = s;  // stored [k][c]
    } else if (tid < 2 * KK * CN + KK) {
        int k = tid - 2 * KK * CN;
        float s = 0.f;
        for (int i = 0; i < CN; i++) s = fmaf(lin0_w[k * CN + i], conv1_b[i], s);
        g_b1[k] = s;
    } else if (tid < 2 * KK * CN + KK + KK * KK) {
        g_M[tid - (2 * KK * CN + KK)] = 0.f;
    } else if (tid < 2 * KK * CN + KK + KK * KK + KK) {
        g_r[tid - (2 * KK * CN + KK + KK * KK)] = 0.f;
    }
}

// ---------------- 2. attn_raw = W1 @ x + b1  (M=64, K=512, N=16384 per batch)
#define A_TN 256
#define A_CH 32
#define A_NC (CN / A_CH)
#define A_SMEM (2 * A_CH * A_TN * 4 + 2 * A_CH * KK * 4)   // 80KB
__global__ __launch_bounds__(256) void attn_gemm_kernel(const float* __restrict__ x) {
    extern __shared__ __align__(16) char sm_a[];
    float (*xs)[A_CH][A_TN] = (float (*)[A_CH][A_TN])sm_a;
    float (*ws)[A_CH][KK]   = (float (*)[A_CH][KK])(sm_a + 2 * A_CH * A_TN * 4);

    int b = blockIdx.y;
    int n0 = blockIdx.x * A_TN;
    int tid = threadIdx.x;
    int tx = tid & 31;
    int ty = tid >> 5;
    const float* xb = x + (size_t)b * CN * NPIX;

    u64 acc[8][4];
#pragma unroll
    for (int i = 0; i < 8; i++)
#pragma unroll
        for (int j = 0; j < 4; j++) acc[i][j] = 0ull;

    auto stage = [&](int ch, int bf) {
        int c0 = ch * A_CH;
#pragma unroll
        for (int j = 0; j < 8; j++) {           // 32*256 floats = 2048 float4 ✓
            int i4 = tid + j * 256;
            int cc = i4 >> 6, nn4 = i4 & 63;
            cp16(&xs[bf][cc][nn4 * 4], &xb[(size_t)(c0 + cc) * NPIX + n0 + nn4 * 4]);
        }
#pragma unroll
        for (int j = 0; j < 2; j++) {           // 32*64 floats = 512 float4 ✓
            int i4 = tid + j * 256;
            int cc = i4 >> 4, k4 = i4 & 15;
            cp16(&ws[bf][cc][k4 * 4], &g_W1t[(c0 + cc) * KK + k4 * 4]);
        }
    };

    stage(0, 0);
    CP_COMMIT;
    for (int ch = 0; ch < A_NC; ch++) {
        int cur = ch & 1;
        if (ch + 1 < A_NC) { stage(ch + 1, cur ^ 1); CP_COMMIT; CP_WAIT1; }
        else               { CP_WAIT0; }
        __syncthreads();
#pragma unroll 8
        for (int cc = 0; cc < A_CH; cc++) {
            ulonglong2 xa = *(const ulonglong2*)&xs[cur][cc][tx * 8];
            ulonglong2 xc = *(const ulonglong2*)&xs[cur][cc][tx * 8 + 4];
            u64 xv[4] = {xa.x, xa.y, xc.x, xc.y};
            float4 w0 = *(const float4*)&ws[cur][cc][ty * 8];
            float4 w1 = *(const float4*)&ws[cur][cc][ty * 8 + 4];
            u64 wv[8] = {pack2(w0.x, w0.x), pack2(w0.y, w0.y),
                         pack2(w0.z, w0.z), pack2(w0.w, w0.w),
                         pack2(w1.x, w1.x), pack2(w1.y, w1.y),
                         pack2(w1.z, w1.z), pack2(w1.w, w1.w)};
#pragma unroll
            for (int ki = 0; ki < 8; ki++)
#pragma unroll
                for (int jp = 0; jp < 4; jp++)
                    acc[ki][jp] = ffma2(wv[ki], xv[jp], acc[ki][jp]);
        }
        __syncthreads();
    }
#pragma unroll
    for (int ki = 0; ki < 8; ki++) {
        int k = ty * 8 + ki;
        float bb = g_b1[k];
        float2 r0 = unpack2(acc[ki][0]), r1 = unpack2(acc[ki][1]);
        float2 r2 = unpack2(acc[ki][2]), r3 = unpack2(acc[ki][3]);
        float4 o0 = {r0.x + bb, r0.y + bb, r1.x + bb, r1.y + bb};
        float4 o1 = {r2.x + bb, r2.y + bb, r3.x + bb, r3.y + bb};
        float* p = g_attn + (size_t)(b * KK + k) * NPIX + n0 + tx * 8;
        *(float4*)p = o0;
        *(float4*)(p + 4) = o1;
    }
}

// ---------------- 3. softmax over n (one block per (b,k) row of 16384) ------
__global__ __launch_bounds__(256) void softmax_kernel() {
    int row = blockIdx.x;
    float* p = g_attn + (size_t)row * NPIX;
    int tid = threadIdx.x;

    float v[64];
    float m = -1e30f;
#pragma unroll
    for (int i = 0; i < 64; i++) {
        v[i] = p[tid + (i << 8)];
        m = fmaxf(m, v[i]);
    }
    __shared__ float red[8];
#pragma unroll
    for (int o = 16; o > 0; o >>= 1) m = fmaxf(m, __shfl_xor_sync(0xffffffffu, m, o));
    if ((tid & 31) == 0) red[tid >> 5] = m;
    __syncthreads();
    if (tid < 32) {
        float t = (tid < 8) ? red[tid] : -1e30f;
#pragma unroll
        for (int o = 4; o > 0; o >>= 1) t = fmaxf(t, __shfl_xor_sync(0xffffffffu, t, o));
        if (tid == 0) red[0] = t;
    }
    __syncthreads();
    m = red[0];
    __syncthreads();

    float s = 0.f;
#pragma unroll
    for (int i = 0; i < 64; i++) {
        v[i] = __expf(v[i] - m);
        s += v[i];
    }
#pragma unroll
    for (int o = 16; o > 0; o >>= 1) s += __shfl_xor_sync(0xffffffffu, s, o);
    if ((tid & 31) == 0) red[tid >> 5] = s;
    __syncthreads();
    if (tid < 32) {
        float t = (tid < 8) ? red[tid] : 0.f;
#pragma unroll
        for (int o = 4; o > 0; o >>= 1) t += __shfl_xor_sync(0xffffffffu, t, o);
        if (tid == 0) red[0] = t;
    }
    __syncthreads();
    float inv = 1.f / red[0];
#pragma unroll
    for (int i = 0; i < 64; i++) p[tid + (i << 8)] = v[i] * inv;
}

// ---------------- 4. stats: M += A~ A~^T, r += rowsum(A~) -------------------
// A~ = attn / (1e-9 + colsum_k). One block per 256-column stripe.
#define S_TN 256
#define S_STRIDE (S_TN + 1)
#define S_SMEM (KK * S_STRIDE * 4)        // ~65.8 KB
__global__ __launch_bounds__(256) void stats_kernel() {
    extern __shared__ __align__(16) float as[];    // [KK][S_STRIDE]
    int b = blockIdx.y;
    int n0 = blockIdx.x * S_TN;
    int tid = threadIdx.x;
    const float* ab = g_attn + (size_t)b * KK * NPIX + n0;

    // stage 64 rows x 256 floats = 4096 float4  (16 iterations x 256 threads ✓)
#pragma unroll
    for (int j = 0; j < 16; j++) {
        int i4 = tid + j * 256;
        int kk = i4 >> 6, nn4 = i4 & 63;
        float4 v = *(const float4*)&ab[(size_t)kk * NPIX + nn4 * 4];
        float* d = &as[kk * S_STRIDE + nn4 * 4];
        d[0] = v.x; d[1] = v.y; d[2] = v.z; d[3] = v.w;
    }
    __syncthreads();

    // per-column renorm in place (thread = column)
    {
        float s = 0.f;
#pragma unroll
        for (int k = 0; k < KK; k++) s += as[k * S_STRIDE + tid];
        float inv = 1.f / (1e-9f + s);
#pragma unroll
        for (int k = 0; k < KK; k++) as[k * S_STRIDE + tid] *= inv;
    }
    __syncthreads();

    // row sums of scaled tile -> g_r   (threads 0..63, staggered start)
    if (tid < KK) {
        float rs = 0.f;
        int base = tid * S_STRIDE;
        int start = (tid * 5) & (S_TN - 1);
#pragma unroll 8
        for (int t = 0; t < S_TN; t++) {
            int nn = start + t; if (nn >= S_TN) nn -= S_TN;
            rs += as[base + nn];
        }
        atomicAdd(&g_r[tid], rs);
    }

    // outer-product accumulation: thread (it,jt) owns 4x4 of M
    int jt = tid & 15, it = tid >> 4;
    float Ml[4][4];
#pragma unroll
    for (int a = 0; a < 4; a++)
#pragma unroll
        for (int q = 0; q < 4; q++) Ml[a][q] = 0.f;
#pragma unroll 4
    for (int nn = 0; nn < S_TN; nn++) {
        float ai[4], aj[4];
#pragma unroll
        for (int a = 0; a < 4; a++) ai[a] = as[(it * 4 + a) * S_STRIDE + nn];
#pragma unroll
        for (int q = 0; q < 4; q++) aj[q] = as[(jt * 4 + q) * S_STRIDE + nn];
#pragma unroll
        for (int a = 0; a < 4; a++)
#pragma unroll
            for (int q = 0; q < 4; q++) Ml[a][q] = fmaf(ai[a], aj[q], Ml[a][q]);
    }
#pragma unroll
    for (int a = 0; a < 4; a++)
#pragma unroll
        for (int q = 0; q < 4; q++)
            atomicAdd(&g_M[(it * 4 + a) * KK + jt * 4 + q], Ml[a][q]);
}

// ---------------- 5. BN scale/shift from quadratic form ---------------------
__global__ __launch_bounds__(128) void bnscale_kernel(const float* __restrict__ gamma,
                                                      const float* __restrict__ beta) {
    __shared__ float Msh[KK * KK];
    int tid = threadIdx.x;
#pragma unroll
    for (int j = 0; j < KK * KK / 128; j++) Msh[tid + j * 128] = g_M[tid + j * 128];
    __syncthreads();

    int c = blockIdx.x * 128 + tid;
    float w[KK];
#pragma unroll
    for (int k = 0; k < KK; k++) w[k] = g_W2t[k * CN + c];
    float mean = 0.f;
#pragma unroll
    for (int k = 0; k < KK; k++) mean = fmaf(w[k], g_r[k], mean);
    mean /= CNT;
    float sumsq = 0.f;
#pragma unroll 2
    for (int i = 0; i < KK; i++) {
        float t = 0.f;
#pragma unroll
        for (int j = 0; j < KK; j++) t = fmaf(Msh[i * KK + j], w[j], t);
        sumsq = fmaf(w[i], t, sumsq);
    }
    float var = sumsq / CNT - mean * mean;
    float sc = gamma[c] * rsqrtf(var + BN_EPS);
    g_scale[c] = sc;
    g_shift[c] = beta[c] - mean * sc;
}

// ---------------- 6. fused: out = relu((W2 @ A~)*sc + sh + x) ---------------
#define B_TN 128
#define B_TC 128
#define B_SMEM (KK * B_TN * 4 + 2 * KK * B_TC * 4 + B_TN * 4)   // 96.5KB
__global__ __launch_bounds__(256) void out_fused_kernel(const float* __restrict__ x,
                                                        float* __restrict__ out) {
    extern __shared__ __align__(16) char sm_b[];
    float (*as)[B_TN]    = (float (*)[B_TN])sm_b;                          // 32KB
    float (*ws)[KK][B_TC] = (float (*)[KK][B_TC])(sm_b + KK * B_TN * 4);   // 2x32KB
    float* dinv          = (float*)(sm_b + KK * B_TN * 4 + 2 * KK * B_TC * 4);

    int b = blockIdx.y;
    int n0 = blockIdx.x * B_TN;
    int tid = threadIdx.x;
    int tx = tid & 15, ty = tid >> 4;
    const float* ab = g_attn + (size_t)b * KK * NPIX;

    // stage attn tile (64x128 floats = 2048 float4 ✓) + weight tile 0 (2048 ✓)
#pragma unroll
    for (int j = 0; j < 8; j++) {
        int i4 = tid + j * 256;
        int kk = i4 >> 5, nn4 = i4 & 31;
        cp16(&as[kk][nn4 * 4], &ab[(size_t)kk * NPIX + n0 + nn4 * 4]);
    }
#pragma unroll
    for (int j = 0; j < 8; j++) {
        int i4 = tid + j * 256;
        int kk = i4 >> 5, cc4 = i4 & 31;
        cp16(&ws[0][kk][cc4 * 4], &g_W2t[kk * CN + cc4 * 4]);
    }
    CP_COMMIT;
    CP_WAIT0;
    __syncthreads();

    if (tid < B_TN) {
        float s = 0.f;
#pragma unroll
        for (int kk = 0; kk < KK; kk++) s += as[kk][tid];
        dinv[tid] = 1.f / (1e-9f + s);
    }
    __syncthreads();
    float inv[8];
#pragma unroll
    for (int j = 0; j < 8; j++) inv[j] = dinv[tx * 8 + j];

    for (int cb = 0; cb < CN / B_TC; cb++) {
        int cur = cb & 1;
        if (cb + 1 < CN / B_TC) {   // prefetch next weight tile
#pragma unroll
            for (int j = 0; j < 8; j++) {
                int i4 = tid + j * 256;
                int kk = i4 >> 5, cc4 = i4 & 31;
                cp16(&ws[cur ^ 1][kk][cc4 * 4],
                     &g_W2t[kk * CN + (cb + 1) * B_TC + cc4 * 4]);
            }
            CP_COMMIT;
        }
        u64 acc[8][4];
#pragma unroll
        for (int i = 0; i < 8; i++)
#pragma unroll
            for (int j = 0; j < 4; j++) acc[i][j] = 0ull;
#pragma unroll 8
        for (int kk = 0; kk < KK; kk++) {
            ulonglong2 aa = *(const ulonglong2*)&as[kk][tx * 8];
            ulonglong2 ac = *(const ulonglong2*)&as[kk][tx * 8 + 4];
            u64 av[4] = {aa.x, aa.y, ac.x, ac.y};
            float4 w0 = *(const float4*)&ws[cur][kk][ty * 8];
            float4 w1 = *(const float4*)&ws[cur][kk][ty * 8 + 4];
            u64 wv[8] = {pack2(w0.x, w0.x), pack2(w0.y, w0.y),
                         pack2(w0.z, w0.z), pack2(w0.w, w0.w),
                         pack2(w1.x, w1.x), pack2(w1.y, w1.y),
                         pack2(w1.z, w1.z), pack2(w1.w, w1.w)};
#pragma unroll
            for (int ki = 0; ki < 8; ki++)
#pragma unroll
                for (int jp = 0; jp < 4; jp++)
                    acc[ki][jp] = ffma2(wv[ki], av[jp], acc[ki][jp]);
        }
        // epilogue: renorm, BN affine, residual, relu -> out
        int c0 = cb * B_TC;
#pragma unroll
        for (int ki = 0; ki < 8; ki++) {
            int c = c0 + ty * 8 + ki;
            float sc = g_scale[c], sh = g_shift[c];
            float2 y0 = unpack2(acc[ki][0]), y1 = unpack2(acc[ki][1]);
            float2 y2 = unpack2(acc[ki][2]), y3 = unpack2(acc[ki][3]);
            size_t off = ((size_t)(b * CN + c)) * NPIX + n0 + tx * 8;
            float4 x0 = *(const float4*)&x[off];
            float4 x1 = *(const float4*)&x[off + 4];
            float4 o0, o1;
            o0.x = fmaxf(fmaf(y0.x * inv[0], sc, sh) + x0.x, 0.f);
            o0.y = fmaxf(fmaf(y0.y * inv[1], sc, sh) + x0.y, 0.f);
            o0.z = fmaxf(fmaf(y1.x * inv[2], sc, sh) + x0.z, 0.f);
            o0.w = fmaxf(fmaf(y1.y * inv[3], sc, sh) + x0.w, 0.f);
            o1.x = fmaxf(fmaf(y2.x * inv[4], sc, sh) + x1.x, 0.f);
            o1.y = fmaxf(fmaf(y2.y * inv[5], sc, sh) + x1.y, 0.f);
            o1.z = fmaxf(fmaf(y3.x * inv[6], sc, sh) + x1.z, 0.f);
            o1.w = fmaxf(fmaf(y3.y * inv[7], sc, sh) + x1.w, 0.f);
            *(float4*)&out[off] = o0;
            *(float4*)&out[off + 4] = o1;
        }
        if (cb + 1 < CN / B_TC) { CP_WAIT0; __syncthreads(); }
    }
}

// ---------------- launch -----------------------------------------------------
extern "C" void kernel_launch(void* const* d_in, const int* in_sizes, int n_in,
                              void* d_out, int out_size) {
    const float* x       = (const float*)d_in[0];
    const float* conv1_w = (const float*)d_in[1];
    const float* conv1_b = (const float*)d_in[2];
    const float* lin0_w  = (const float*)d_in[3];
    const float* lin1_w  = (const float*)d_in[4];
    const float* conv2_w = (const float*)d_in[5];
    const float* gamma   = (const float*)d_in[6];
    const float* beta    = (const float*)d_in[7];
    float* out = (float*)d_out;

    cudaFuncSetAttribute(attn_gemm_kernel,
                         cudaFuncAttributeMaxDynamicSharedMemorySize, A_SMEM);
    cudaFuncSetAttribute(stats_kernel,
                         cudaFuncAttributeMaxDynamicSharedMemorySize, S_SMEM);
    cudaFuncSetAttribute(out_fused_kernel,
                         cudaFuncAttributeMaxDynamicSharedMemorySize, B_SMEM);

    int prep_n = 2 * KK * CN + KK + KK * KK + KK;
    prep_kernel<<<(prep_n + 255) / 256, 256>>>(conv1_w, conv1_b, lin0_w, lin1_w, conv2_w);
    attn_gemm_kernel<<<dim3(NPIX / A_TN, BB), 256, A_SMEM>>>(x);
    softmax_kernel<<<BB * KK, 256>>>();
    stats_kernel<<<dim3(NPIX / S_TN, BB), 256, S_SMEM>>>();
    bnscale_kernel<<<CN / 128, 128>>>(gamma, beta);
    out_fused_kernel<<<dim3(NPIX / B_TN, BB), 256, B_SMEM>>>(x, out);
}

// round 9
// speedup vs baseline: 1.8257x; 1.2103x over previous
#include <cuda_runtime.h>

#define CN 512
#define KK 64
#define NPIX 16384
#define BB 8
#define BN_EPS 1e-5f
#define CNT ((float)(BB * NPIX))

typedef unsigned long long u64;

__device__ __forceinline__ u64 ffma2(u64 a, u64 b, u64 c) {
    u64 d;
    asm("fma.rn.f32x2 %0, %1, %2, %3;" : "=l"(d) : "l"(a), "l"(b), "l"(c));
    return d;
}
__device__ __forceinline__ u64 pack2(float x, float y) {
    u64 v; asm("mov.b64 %0, {%1, %2};" : "=l"(v) : "f"(x), "f"(y)); return v;
}
__device__ __forceinline__ float2 unpack2(u64 v) {
    float2 f; asm("mov.b64 {%0, %1}, %2;" : "=f"(f.x), "=f"(f.y) : "l"(v)); return f;
}
__device__ __forceinline__ void cp16(void* smem_dst, const void* gmem_src) {
    unsigned s = (unsigned)__cvta_generic_to_shared(smem_dst);
    asm volatile("cp.async.cg.shared.global [%0], [%1], 16;" :: "r"(s), "l"(gmem_src));
}
#define CP_COMMIT asm volatile("cp.async.commit_group;")
#define CP_WAIT0  asm volatile("cp.async.wait_group 0;")
#define CP_WAIT1  asm volatile("cp.async.wait_group 1;")

// ---------------- scratch (static device globals; no allocation) -------------
__device__ float g_W1t[CN * KK];         // (lin0_w @ conv1_w)^T  [c][k]
__device__ float g_b1[KK];               // lin0_w @ conv1_b
__device__ float g_W2t[KK * CN];         // (conv2_w @ lin1_w)^T  [k][c]
__device__ float g_attn[(size_t)BB * KK * NPIX];        // 32 MB (exp, then Atilde)
__device__ float g_rowsum[BB * KK];      // per-row sum of exp
__device__ float g_M[KK * KK];           // sum_b  A~ A~^T
__device__ float g_r[KK];                // sum_{b,n} A~
__device__ float g_scale[CN];
__device__ float g_shift[CN];

// ---------------- 1. tiled prep: folded weights + zero accumulators ---------
// blocks 0-7: W1t c-tiles; 8-15: W2t c-tiles; 16: b1 + zeroing
__global__ __launch_bounds__(256) void prep_kernel(const float* __restrict__ conv1_w,
                                                   const float* __restrict__ conv1_b,
                                                   const float* __restrict__ lin0_w,
                                                   const float* __restrict__ lin1_w,
                                                   const float* __restrict__ conv2_w) {
    int blk = blockIdx.x;
    int tid = threadIdx.x;
    if (blk < 16) {
        __shared__ float Ct[32][65];
        __shared__ float Lt[32][65];
        int tx = tid & 15, tyc = tid >> 4;
        float acc[4][4];
#pragma unroll
        for (int a = 0; a < 4; a++)
#pragma unroll
            for (int q = 0; q < 4; q++) acc[a][q] = 0.f;
        if (blk < 8) {
            // W1t[c][k] = sum_i lin0_w[k*CN+i] * conv1_w[i*CN+c], c tile = blk*64
            int c0 = blk * 64;
            for (int i0 = 0; i0 < CN; i0 += 32) {
#pragma unroll
                for (int j = 0; j < 8; j++) {            // 2048 elems each matrix
                    int idx = tid + j * 256;
                    { int ii = idx >> 6, cc = idx & 63;   // Ct coalesced in cc
                      Ct[ii][cc] = conv1_w[(i0 + ii) * CN + c0 + cc]; }
                    { int ii = idx & 31, kk = idx >> 5;   // Lt coalesced in ii
                      Lt[ii][kk] = lin0_w[kk * CN + i0 + ii]; }
                }
                __syncthreads();
#pragma unroll
                for (int ii = 0; ii < 32; ii++) {
                    float cv[4], lv[4];
#pragma unroll
                    for (int a = 0; a < 4; a++) cv[a] = Ct[ii][tyc * 4 + a];
#pragma unroll
                    for (int q = 0; q < 4; q++) lv[q] = Lt[ii][tx * 4 + q];
#pragma unroll
                    for (int a = 0; a < 4; a++)
#pragma unroll
                        for (int q = 0; q < 4; q++) acc[a][q] = fmaf(cv[a], lv[q], acc[a][q]);
                }
                __syncthreads();
            }
#pragma unroll
            for (int a = 0; a < 4; a++)
#pragma unroll
                for (int q = 0; q < 4; q++)
                    g_W1t[(c0 + tyc * 4 + a) * KK + tx * 4 + q] = acc[a][q];
        } else {
            // W2t[k][c] = sum_i conv2_w[c*CN+i] * lin1_w[i*KK+k], c tile = (blk-8)*64
            int c0 = (blk - 8) * 64;
            for (int i0 = 0; i0 < CN; i0 += 32) {
#pragma unroll
                for (int j = 0; j < 8; j++) {
                    int idx = tid + j * 256;
                    { int ii = idx & 31, cc = idx >> 5;   // conv2_w rows coalesced in ii
                      Ct[ii][cc] = conv2_w[(c0 + cc) * CN + i0 + ii]; }
                    { int kk = idx & 63, ii = idx >> 6;   // lin1_w coalesced in kk
                      Lt[ii][kk] = lin1_w[(i0 + ii) * KK + kk]; }
                }
                __syncthreads();
#pragma unroll
                for (int ii = 0; ii < 32; ii++) {
                    float lv[4], cv[4];
#pragma unroll
                    for (int a = 0; a < 4; a++) lv[a] = Lt[ii][tx * 4 + a];    // k
#pragma unroll
                    for (int q = 0; q < 4; q++) cv[q] = Ct[ii][tyc * 4 + q];   // c
#pragma unroll
                    for (int a = 0; a < 4; a++)
#pragma unroll
                        for (int q = 0; q < 4; q++) acc[a][q] = fmaf(lv[a], cv[q], acc[a][q]);
                }
                __syncthreads();
            }
#pragma unroll
            for (int a = 0; a < 4; a++)
#pragma unroll
                for (int q = 0; q < 4; q++)
                    g_W2t[(tx * 4 + a) * CN + c0 + tyc * 4 + q] = acc[a][q];
        }
    } else {
        // b1 + zero M, r, rowsum
        if (tid < KK) {
            float s = 0.f;
            for (int i = 0; i < CN; i++) s = fmaf(lin0_w[tid * CN + i], conv1_b[i], s);
            g_b1[tid] = s;
        }
        for (int i = tid; i < KK * KK; i += 256) g_M[i] = 0.f;
        if (tid < KK) g_r[tid] = 0.f;
        for (int i = tid; i < BB * KK; i += 256) g_rowsum[i] = 0.f;
    }
}

// ---------------- 2. attn exp = exp(W1 @ x + b1); rowsum atomics ------------
#define A_TN 256
#define A_CH 32
#define A_NC (CN / A_CH)
#define A_SMEM (2 * A_CH * A_TN * 4 + 2 * A_CH * KK * 4)   // 80KB
__global__ __launch_bounds__(256) void attn_gemm_kernel(const float* __restrict__ x) {
    extern __shared__ __align__(16) char sm_a[];
    float (*xs)[A_CH][A_TN] = (float (*)[A_CH][A_TN])sm_a;
    float (*ws)[A_CH][KK]   = (float (*)[A_CH][KK])(sm_a + 2 * A_CH * A_TN * 4);

    int b = blockIdx.y;
    int n0 = blockIdx.x * A_TN;
    int tid = threadIdx.x;
    int tx = tid & 31;
    int ty = tid >> 5;
    const float* xb = x + (size_t)b * CN * NPIX;

    u64 acc[8][4];
#pragma unroll
    for (int i = 0; i < 8; i++)
#pragma unroll
        for (int j = 0; j < 4; j++) acc[i][j] = 0ull;

    auto stage = [&](int ch, int bf) {
        int c0 = ch * A_CH;
#pragma unroll
        for (int j = 0; j < 8; j++) {           // 2048 float4 ✓
            int i4 = tid + j * 256;
            int cc = i4 >> 6, nn4 = i4 & 63;
            cp16(&xs[bf][cc][nn4 * 4], &xb[(size_t)(c0 + cc) * NPIX + n0 + nn4 * 4]);
        }
#pragma unroll
        for (int j = 0; j < 2; j++) {           // 512 float4 ✓
            int i4 = tid + j * 256;
            int cc = i4 >> 4, k4 = i4 & 15;
            cp16(&ws[bf][cc][k4 * 4], &g_W1t[(c0 + cc) * KK + k4 * 4]);
        }
    };

    stage(0, 0);
    CP_COMMIT;
    for (int ch = 0; ch < A_NC; ch++) {
        int cur = ch & 1;
        if (ch + 1 < A_NC) { stage(ch + 1, cur ^ 1); CP_COMMIT; CP_WAIT1; }
        else               { CP_WAIT0; }
        __syncthreads();
#pragma unroll 8
        for (int cc = 0; cc < A_CH; cc++) {
            ulonglong2 xa = *(const ulonglong2*)&xs[cur][cc][tx * 8];
            ulonglong2 xc = *(const ulonglong2*)&xs[cur][cc][tx * 8 + 4];
            u64 xv[4] = {xa.x, xa.y, xc.x, xc.y};
            float4 w0 = *(const float4*)&ws[cur][cc][ty * 8];
            float4 w1 = *(const float4*)&ws[cur][cc][ty * 8 + 4];
            u64 wv[8] = {pack2(w0.x, w0.x), pack2(w0.y, w0.y),
                         pack2(w0.z, w0.z), pack2(w0.w, w0.w),
                         pack2(w1.x, w1.x), pack2(w1.y, w1.y),
                         pack2(w1.z, w1.z), pack2(w1.w, w1.w)};
#pragma unroll
            for (int ki = 0; ki < 8; ki++)
#pragma unroll
                for (int jp = 0; jp < 4; jp++)
                    acc[ki][jp] = ffma2(wv[ki], xv[jp], acc[ki][jp]);
        }
        __syncthreads();
    }
    // epilogue: exp(v + b1) (no-max softmax numerator), store, rowsum atomics
#pragma unroll
    for (int ki = 0; ki < 8; ki++) {
        int k = ty * 8 + ki;
        float bb = g_b1[k];
        float2 r0 = unpack2(acc[ki][0]), r1 = unpack2(acc[ki][1]);
        float2 r2 = unpack2(acc[ki][2]), r3 = unpack2(acc[ki][3]);
        float4 o0 = {__expf(r0.x + bb), __expf(r0.y + bb),
                     __expf(r1.x + bb), __expf(r1.y + bb)};
        float4 o1 = {__expf(r2.x + bb), __expf(r2.y + bb),
                     __expf(r3.x + bb), __expf(r3.y + bb)};
        float* p = g_attn + (size_t)(b * KK + k) * NPIX + n0 + tx * 8;
        *(float4*)p = o0;
        *(float4*)(p + 4) = o1;
        float s = o0.x + o0.y + o0.z + o0.w + o1.x + o1.y + o1.z + o1.w;
#pragma unroll
        for (int o = 16; o > 0; o >>= 1) s += __shfl_xor_sync(0xffffffffu, s, o);
        if (tx == 0) atomicAdd(&g_rowsum[b * KK + k], s);
    }
}

// ---------------- 3. stats + full renorm: writes Atilde, accumulates M,r ----
#define S_TN 256
#define S_STRIDE (S_TN + 1)
#define S_SMEM (KK * S_STRIDE * 4)        // ~65.8 KB
__global__ __launch_bounds__(256) void stats_kernel() {
    extern __shared__ __align__(16) float as[];    // [KK][S_STRIDE]
    __shared__ float invrow[KK];
    int b = blockIdx.y;
    int n0 = blockIdx.x * S_TN;
    int tid = threadIdx.x;
    float* ab = g_attn + (size_t)b * KK * NPIX + n0;

    if (tid < KK) invrow[tid] = 1.f / g_rowsum[b * KK + tid];
    // stage 64 x 256 floats = 4096 float4 (16 x 256 ✓)
#pragma unroll
    for (int j = 0; j < 16; j++) {
        int i4 = tid + j * 256;
        int kk = i4 >> 6, nn4 = i4 & 63;
        float4 v = *(const float4*)&ab[(size_t)kk * NPIX + nn4 * 4];
        float* d = &as[kk * S_STRIDE + nn4 * 4];
        d[0] = v.x; d[1] = v.y; d[2] = v.z; d[3] = v.w;
    }
    __syncthreads();

    // per-column: softmax-normalize rows, then L1-renorm over k (thread = col)
    {
        float s = 0.f;
#pragma unroll
        for (int k = 0; k < KK; k++) {
            float v = as[k * S_STRIDE + tid] * invrow[k];
            as[k * S_STRIDE + tid] = v;
            s += v;
        }
        float inv = 1.f / (1e-9f + s);
#pragma unroll
        for (int k = 0; k < KK; k++) as[k * S_STRIDE + tid] *= inv;
    }
    __syncthreads();

    // write back Atilde (same pattern as staging ✓)
#pragma unroll
    for (int j = 0; j < 16; j++) {
        int i4 = tid + j * 256;
        int kk = i4 >> 6, nn4 = i4 & 63;
        float* s = &as[kk * S_STRIDE + nn4 * 4];
        float4 v = {s[0], s[1], s[2], s[3]};
        *(float4*)&ab[(size_t)kk * NPIX + nn4 * 4] = v;
    }

    // row sums -> g_r  (threads 0..63, staggered)
    if (tid < KK) {
        float rs = 0.f;
        int base = tid * S_STRIDE;
        int start = (tid * 5) & (S_TN - 1);
#pragma unroll 8
        for (int t = 0; t < S_TN; t++) {
            int nn = start + t; if (nn >= S_TN) nn -= S_TN;
            rs += as[base + nn];
        }
        atomicAdd(&g_r[tid], rs);
    }

    // outer product: thread (it,jt) owns 4x4 of M
    int jt = tid & 15, it = tid >> 4;
    float Ml[4][4];
#pragma unroll
    for (int a = 0; a < 4; a++)
#pragma unroll
        for (int q = 0; q < 4; q++) Ml[a][q] = 0.f;
#pragma unroll 4
    for (int nn = 0; nn < S_TN; nn++) {
        float ai[4], aj[4];
#pragma unroll
        for (int a = 0; a < 4; a++) ai[a] = as[(it * 4 + a) * S_STRIDE + nn];
#pragma unroll
        for (int q = 0; q < 4; q++) aj[q] = as[(jt * 4 + q) * S_STRIDE + nn];
#pragma unroll
        for (int a = 0; a < 4; a++)
#pragma unroll
            for (int q = 0; q < 4; q++) Ml[a][q] = fmaf(ai[a], aj[q], Ml[a][q]);
    }
#pragma unroll
    for (int a = 0; a < 4; a++)
#pragma unroll
        for (int q = 0; q < 4; q++)
            atomicAdd(&g_M[(it * 4 + a) * KK + jt * 4 + q], Ml[a][q]);
}

// ---------------- 4. BN scale/shift from quadratic form ---------------------
__global__ __launch_bounds__(128) void bnscale_kernel(const float* __restrict__ gamma,
                                                      const float* __restrict__ beta) {
    __shared__ float Msh[KK * KK];
    int tid = threadIdx.x;
#pragma unroll
    for (int j = 0; j < KK * KK / 128; j++) Msh[tid + j * 128] = g_M[tid + j * 128];
    __syncthreads();

    int c = blockIdx.x * 128 + tid;
    float w[KK];
#pragma unroll
    for (int k = 0; k < KK; k++) w[k] = g_W2t[k * CN + c];
    float mean = 0.f;
#pragma unroll
    for (int k = 0; k < KK; k++) mean = fmaf(w[k], g_r[k], mean);
    mean /= CNT;
    float sumsq = 0.f;
#pragma unroll 2
    for (int i = 0; i < KK; i++) {
        float t = 0.f;
#pragma unroll
        for (int j = 0; j < KK; j++) t = fmaf(Msh[i * KK + j], w[j], t);
        sumsq = fmaf(w[i], t, sumsq);
    }
    float var = sumsq / CNT - mean * mean;
    float sc = gamma[c] * rsqrtf(var + BN_EPS);
    g_scale[c] = sc;
    g_shift[c] = beta[c] - mean * sc;
}

// ---------------- 5. fused: out = relu((W2 @ Atilde)*sc + sh + x) -----------
#define B_TN 128
#define B_TC 128
#define B_SMEM (KK * B_TN * 4 + 2 * KK * B_TC * 4)   // 96KB
__global__ __launch_bounds__(256) void out_fused_kernel(const float* __restrict__ x,
                                                        float* __restrict__ out) {
    extern __shared__ __align__(16) char sm_b[];
    float (*as)[B_TN]     = (float (*)[B_TN])sm_b;                          // 32KB
    float (*ws)[KK][B_TC] = (float (*)[KK][B_TC])(sm_b + KK * B_TN * 4);    // 2x32KB

    int b = blockIdx.y;
    int n0 = blockIdx.x * B_TN;
    int tid = threadIdx.x;
    int tx = tid & 15, ty = tid >> 4;
    const float* ab = g_attn + (size_t)b * KK * NPIX;

    // stage Atilde tile (2048 float4 ✓) + weight tile 0 (2048 ✓)
#pragma unroll
    for (int j = 0; j < 8; j++) {
        int i4 = tid + j * 256;
        int kk = i4 >> 5, nn4 = i4 & 31;
        cp16(&as[kk][nn4 * 4], &ab[(size_t)kk * NPIX + n0 + nn4 * 4]);
    }
#pragma unroll
    for (int j = 0; j < 8; j++) {
        int i4 = tid + j * 256;
        int kk = i4 >> 5, cc4 = i4 & 31;
        cp16(&ws[0][kk][cc4 * 4], &g_W2t[kk * CN + cc4 * 4]);
    }
    CP_COMMIT;
    CP_WAIT0;
    __syncthreads();

    for (int cb = 0; cb < CN / B_TC; cb++) {
        int cur = cb & 1;
        if (cb + 1 < CN / B_TC) {   // prefetch next weight tile
#pragma unroll
            for (int j = 0; j < 8; j++) {
                int i4 = tid + j * 256;
                int kk = i4 >> 5, cc4 = i4 & 31;
                cp16(&ws[cur ^ 1][kk][cc4 * 4],
                     &g_W2t[kk * CN + (cb + 1) * B_TC + cc4 * 4]);
            }
            CP_COMMIT;
        }
        u64 acc[8][4];
#pragma unroll
        for (int i = 0; i < 8; i++)
#pragma unroll
            for (int j = 0; j < 4; j++) acc[i][j] = 0ull;
#pragma unroll 8
        for (int kk = 0; kk < KK; kk++) {
            ulonglong2 aa = *(const ulonglong2*)&as[kk][tx * 8];
            ulonglong2 ac = *(const ulonglong2*)&as[kk][tx * 8 + 4];
            u64 av[4] = {aa.x, aa.y, ac.x, ac.y};
            float4 w0 = *(const float4*)&ws[cur][kk][ty * 8];
            float4 w1 = *(const float4*)&ws[cur][kk][ty * 8 + 4];
            u64 wv[8] = {pack2(w0.x, w0.x), pack2(w0.y, w0.y),
                         pack2(w0.z, w0.z), pack2(w0.w, w0.w),
                         pack2(w1.x, w1.x), pack2(w1.y, w1.y),
                         pack2(w1.z, w1.z), pack2(w1.w, w1.w)};
#pragma unroll
            for (int ki = 0; ki < 8; ki++)
#pragma unroll
                for (int jp = 0; jp < 4; jp++)
                    acc[ki][jp] = ffma2(wv[ki], av[jp], acc[ki][jp]);
        }
        // epilogue: BN affine, residual, relu -> out
        int c0 = cb * B_TC;
#pragma unroll
        for (int ki = 0; ki < 8; ki++) {
            int c = c0 + ty * 8 + ki;
            float sc = g_scale[c], sh = g_shift[c];
            float2 y0 = unpack2(acc[ki][0]), y1 = unpack2(acc[ki][1]);
            float2 y2 = unpack2(acc[ki][2]), y3 = unpack2(acc[ki][3]);
            size_t off = ((size_t)(b * CN + c)) * NPIX + n0 + tx * 8;
            float4 x0 = *(const float4*)&x[off];
            float4 x1 = *(const float4*)&x[off + 4];
            float4 o0, o1;
            o0.x = fmaxf(fmaf(y0.x, sc, sh) + x0.x, 0.f);
            o0.y = fmaxf(fmaf(y0.y, sc, sh) + x0.y, 0.f);
            o0.z = fmaxf(fmaf(y1.x, sc, sh) + x0.z, 0.f);
            o0.w = fmaxf(fmaf(y1.y, sc, sh) + x0.w, 0.f);
            o1.x = fmaxf(fmaf(y2.x, sc, sh) + x1.x, 0.f);
            o1.y = fmaxf(fmaf(y2.y, sc, sh) + x1.y, 0.f);
            o1.z = fmaxf(fmaf(y3.x, sc, sh) + x1.z, 0.f);
            o1.w = fmaxf(fmaf(y3.y, sc, sh) + x1.w, 0.f);
            *(float4*)&out[off] = o0;
            *(float4*)&out[off + 4] = o1;
        }
        if (cb + 1 < CN / B_TC) { CP_WAIT0; __syncthreads(); }
    }
}

// ---------------- launch -----------------------------------------------------
extern "C" void kernel_launch(void* const* d_in, const int* in_sizes, int n_in,
                              void* d_out, int out_size) {
    const float* x       = (const float*)d_in[0];
    const float* conv1_w = (const float*)d_in[1];
    const float* conv1_b = (const float*)d_in[2];
    const float* lin0_w  = (const float*)d_in[3];
    const float* lin1_w  = (const float*)d_in[4];
    const float* conv2_w = (const float*)d_in[5];
    const float* gamma   = (const float*)d_in[6];
    const float* beta    = (const float*)d_in[7];
    float* out = (float*)d_out;

    cudaFuncSetAttribute(attn_gemm_kernel,
                         cudaFuncAttributeMaxDynamicSharedMemorySize, A_SMEM);
    cudaFuncSetAttribute(stats_kernel,
                         cudaFuncAttributeMaxDynamicSharedMemorySize, S_SMEM);
    cudaFuncSetAttribute(out_fused_kernel,
                         cudaFuncAttributeMaxDynamicSharedMemorySize, B_SMEM);

    prep_kernel<<<17, 256>>>(conv1_w, conv1_b, lin0_w, lin1_w, conv2_w);
    attn_gemm_kernel<<<dim3(NPIX / A_TN, BB), 256, A_SMEM>>>(x);
    stats_kernel<<<dim3(NPIX / S_TN, BB), 256, S_SMEM>>>();
    bnscale_kernel<<<CN / 128, 128>>>(gamma, beta);
    out_fused_kernel<<<dim3(NPIX / B_TN, BB), 256, B_SMEM>>>(x, out);
}